// round 13
// baseline (speedup 1.0000x reference)
#include <cuda_runtime.h>
#include <math.h>
#include <stdint.h>

#define BN_ 8
#define L_ 2048
#define D_ 1024

// Scratch
__device__ float g_E[(size_t)BN_ * L_ * L_];
__device__ float g_P[(size_t)BN_ * L_ * L_];   // row-softmax(E), tf32-rounded
__device__ float g_Q[(size_t)BN_ * L_ * L_];   // col-softmax(E), tf32-rounded
__device__ float g_At[(size_t)BN_ * L_ * D_];  // tf32-rounded A
__device__ float g_Bt[(size_t)BN_ * L_ * D_];  // tf32-rounded B
__device__ float g_rmax[BN_ * L_];
__device__ float g_rsumInv[BN_ * L_];
__device__ float g_cmax[BN_ * L_];
__device__ float g_csumInv[BN_ * L_];

#define NEG_INF __int_as_float(0xff800000)

static __device__ __forceinline__ uint32_t smem_u32(const void* p) {
    uint32_t a;
    asm("{ .reg .u64 t; cvta.to.shared.u64 t, %1; cvt.u32.u64 %0, t; }"
        : "=r"(a) : "l"(p));
    return a;
}
static __device__ __forceinline__ uint32_t cvt_tf32(float x) {
    uint32_t h;
    asm("cvt.rna.tf32.f32 %0, %1;" : "=r"(h) : "f"(x));
    return h;
}
static __device__ __forceinline__ float tf32r(float x) {
    return __uint_as_float(cvt_tf32(x));
}
static __device__ __forceinline__ uint32_t bf2(float lo, float hi) {
    uint32_t d;
    asm("cvt.rn.bf16x2.f32 %0, %1, %2;" : "=r"(d) : "f"(hi), "f"(lo));
    return d;
}
static __device__ __forceinline__ float bflo(uint32_t p) { return __uint_as_float(p << 16); }
static __device__ __forceinline__ float bfhi(uint32_t p) { return __uint_as_float(p & 0xffff0000u); }

static __device__ __forceinline__ void mma8(float c[4], const uint32_t a[4],
                                            const uint32_t b[2]) {
    asm volatile(
        "mma.sync.aligned.m16n8k8.row.col.f32.tf32.tf32.f32 "
        "{%0,%1,%2,%3},{%4,%5,%6,%7},{%8,%9},{%0,%1,%2,%3};"
        : "+f"(c[0]), "+f"(c[1]), "+f"(c[2]), "+f"(c[3])
        : "r"(a[0]), "r"(a[1]), "r"(a[2]), "r"(a[3]), "r"(b[0]), "r"(b[1]));
}
static __device__ __forceinline__ void mma16(float c[4], const uint32_t a[4],
                                             const uint32_t b[2]) {
    asm volatile(
        "mma.sync.aligned.m16n8k16.row.col.f32.bf16.bf16.f32 "
        "{%0,%1,%2,%3},{%4,%5,%6,%7},{%8,%9},{%0,%1,%2,%3};"
        : "+f"(c[0]), "+f"(c[1]), "+f"(c[2]), "+f"(c[3])
        : "r"(a[0]), "r"(a[1]), "r"(a[2]), "r"(a[3]), "r"(b[0]), "r"(b[1]));
}
static __device__ __forceinline__ void cpa16(uint32_t dst, const void* src) {
    asm volatile("cp.async.cg.shared.global [%0], [%1], 16;" :: "r"(dst), "l"(src));
}
#define CP_COMMIT() asm volatile("cp.async.commit_group;" ::: "memory")
#define CP_WAIT1()  asm volatile("cp.async.wait_group 1;" ::: "memory")
#define CP_WAIT0()  asm volatile("cp.async.wait_group 0;" ::: "memory")

// ---------------------------------------------------------------------------
// Round A, B to tf32 once (for phase-2).
// ---------------------------------------------------------------------------
__global__ __launch_bounds__(256) void k_round(const float* __restrict__ A,
                                               const float* __restrict__ B) {
    const size_t i = ((size_t)blockIdx.x * 256 + threadIdx.x) * 4;
    float4 a = *(const float4*)(A + i);
    float4 b = *(const float4*)(B + i);
    a.x = tf32r(a.x); a.y = tf32r(a.y); a.z = tf32r(a.z); a.w = tf32r(a.w);
    b.x = tf32r(b.x); b.y = tf32r(b.y); b.z = tf32r(b.z); b.w = tf32r(b.w);
    *(float4*)(g_At + i) = a;
    *(float4*)(g_Bt + i) = b;
}

// ---------------------------------------------------------------------------
// E = A @ B^T via 3xBF16 (hh + hl + lh), m16n8k16. 128x128 tile, BK=32,
// 8 warps (4m x 2n), 256 thr.  Register split staging (R11 form).
// ---------------------------------------------------------------------------
#define EP2 20
#define EB2 (128 * EP2)
__global__ __launch_bounds__(256, 1) void k_gemm_e(const float* __restrict__ A,
                                                   const float* __restrict__ B) {
    extern __shared__ uint32_t smu[];
    uint32_t* tAH = smu;
    uint32_t* tAL = smu + 2 * EB2;
    uint32_t* tBH = smu + 4 * EB2;
    uint32_t* tBL = smu + 6 * EB2;
    const int tid = threadIdx.x, lane = tid & 31, wid = tid >> 5;
    const int wm = wid & 3, wn = wid >> 2;
    const int q = lane >> 2, r = lane & 3;
    const int b = blockIdx.z, i0 = blockIdx.y * 128, j0 = blockIdx.x * 128;
    const float* Ab = A + ((size_t)b * L_ + i0) * D_;
    const float* Bb = B + ((size_t)b * L_ + j0) * D_;

    float acc[2][8][4];
    #pragma unroll
    for (int mt = 0; mt < 2; mt++)
        #pragma unroll
        for (int nt = 0; nt < 8; nt++)
            #pragma unroll
            for (int e = 0; e < 4; e++) acc[mt][nt][e] = 0.f;

    const int srow = tid >> 2;
    const int sc4 = tid & 3;

    float4 av[2][2], bv[2][2];
    #define LOADREGS_E(c)                                                              \
        do {                                                                           \
            const int _k0 = (c) * 32 + sc4 * 8;                                        \
            _Pragma("unroll")                                                          \
            for (int t = 0; t < 2; t++) {                                              \
                int row = t * 64 + srow;                                               \
                av[t][0] = *(const float4*)(Ab + (size_t)row * D_ + _k0);              \
                av[t][1] = *(const float4*)(Ab + (size_t)row * D_ + _k0 + 4);          \
                bv[t][0] = *(const float4*)(Bb + (size_t)row * D_ + _k0);              \
                bv[t][1] = *(const float4*)(Bb + (size_t)row * D_ + _k0 + 4);          \
            }                                                                          \
        } while (0)
    #define PACKSTORE(dstH, dstL, v0, v1, off)                                          \
        do {                                                                            \
            uint32_t h0 = bf2((v0).x, (v0).y), h1 = bf2((v0).z, (v0).w);                \
            uint32_t h2 = bf2((v1).x, (v1).y), h3 = bf2((v1).z, (v1).w);                \
            uint32_t l0 = bf2((v0).x - bflo(h0), (v0).y - bfhi(h0));                    \
            uint32_t l1 = bf2((v0).z - bflo(h1), (v0).w - bfhi(h1));                    \
            uint32_t l2 = bf2((v1).x - bflo(h2), (v1).y - bfhi(h2));                    \
            uint32_t l3 = bf2((v1).z - bflo(h3), (v1).w - bfhi(h3));                    \
            *(uint4*)((dstH) + (off)) = make_uint4(h0, h1, h2, h3);                     \
            *(uint4*)((dstL) + (off)) = make_uint4(l0, l1, l2, l3);                     \
        } while (0)
    #define STAGE_E(bufn)                                                              \
        do {                                                                           \
            _Pragma("unroll")                                                          \
            for (int t = 0; t < 2; t++) {                                              \
                int row = t * 64 + srow;                                               \
                int off = (bufn) * EB2 + row * EP2 + sc4 * 4;                          \
                PACKSTORE(tAH, tAL, av[t][0], av[t][1], off);                          \
                PACKSTORE(tBH, tBL, bv[t][0], bv[t][1], off);                          \
            }                                                                          \
        } while (0)

    LOADREGS_E(0);
    for (int c = 0; c < 32; c++) {
        const int buf = c & 1;
        STAGE_E(buf);
        if (c + 1 < 32) LOADREGS_E(c + 1);
        __syncthreads();
        const uint32_t* AH_ = tAH + buf * EB2;
        const uint32_t* AL_ = tAL + buf * EB2;
        const uint32_t* BH_ = tBH + buf * EB2;
        const uint32_t* BL_ = tBL + buf * EB2;
        #pragma unroll
        for (int ks = 0; ks < 2; ks++) {
            const int kb2 = ks * 8;
            uint32_t ah[2][4], al[2][4], bh[8][2], bl[8][2];
            #pragma unroll
            for (int mt = 0; mt < 2; mt++) {
                const int rb = wm * 32 + mt * 16;
                ah[mt][0] = AH_[(rb + q) * EP2 + kb2 + r];
                ah[mt][1] = AH_[(rb + q + 8) * EP2 + kb2 + r];
                ah[mt][2] = AH_[(rb + q) * EP2 + kb2 + r + 4];
                ah[mt][3] = AH_[(rb + q + 8) * EP2 + kb2 + r + 4];
                al[mt][0] = AL_[(rb + q) * EP2 + kb2 + r];
                al[mt][1] = AL_[(rb + q + 8) * EP2 + kb2 + r];
                al[mt][2] = AL_[(rb + q) * EP2 + kb2 + r + 4];
                al[mt][3] = AL_[(rb + q + 8) * EP2 + kb2 + r + 4];
            }
            #pragma unroll
            for (int nt = 0; nt < 8; nt++) {
                const int nb = wn * 64 + nt * 8;
                bh[nt][0] = BH_[(nb + q) * EP2 + kb2 + r];
                bh[nt][1] = BH_[(nb + q) * EP2 + kb2 + r + 4];
                bl[nt][0] = BL_[(nb + q) * EP2 + kb2 + r];
                bl[nt][1] = BL_[(nb + q) * EP2 + kb2 + r + 4];
            }
            #pragma unroll
            for (int mt = 0; mt < 2; mt++)
                #pragma unroll
                for (int nt = 0; nt < 8; nt++) {
                    mma16(acc[mt][nt], al[mt], bh[nt]);
                    mma16(acc[mt][nt], ah[mt], bl[nt]);
                    mma16(acc[mt][nt], ah[mt], bh[nt]);
                }
        }
        __syncthreads();
    }
    #undef STAGE_E
    #undef PACKSTORE
    #undef LOADREGS_E

    float* Eb = g_E + ((size_t)b * L_ + i0) * L_ + j0;
    #pragma unroll
    for (int mt = 0; mt < 2; mt++)
        #pragma unroll
        for (int nt = 0; nt < 8; nt++) {
            int row = wm * 32 + mt * 16 + q;
            int col = wn * 64 + nt * 8 + r * 2;
            *(float2*)(Eb + (size_t)row * L_ + col) =
                make_float2(acc[mt][nt][0], acc[mt][nt][1]);
            *(float2*)(Eb + (size_t)(row + 8) * L_ + col) =
                make_float2(acc[mt][nt][2], acc[mt][nt][3]);
        }
}

// ---------------------------------------------------------------------------
// Row / col softmax stats
// ---------------------------------------------------------------------------
__global__ __launch_bounds__(256) void k_rowstats() {
    const int b = blockIdx.y, rrow = blockIdx.x;
    const float* row = g_E + (size_t)(b * L_ + rrow) * L_;
    const int tid = threadIdx.x;
    __shared__ float red[256];

    float m = NEG_INF;
    for (int j = tid * 4; j < L_; j += 1024) {
        float4 v = *(const float4*)(row + j);
        m = fmaxf(m, fmaxf(fmaxf(v.x, v.y), fmaxf(v.z, v.w)));
    }
    red[tid] = m; __syncthreads();
    for (int s = 128; s >= 1; s >>= 1) {
        if (tid < s) red[tid] = fmaxf(red[tid], red[tid + s]);
        __syncthreads();
    }
    const float M = red[0];
    __syncthreads();

    float sum = 0.f;
    for (int j = tid * 4; j < L_; j += 1024) {
        float4 v = *(const float4*)(row + j);
        sum += __expf(v.x - M) + __expf(v.y - M) + __expf(v.z - M) + __expf(v.w - M);
    }
    red[tid] = sum; __syncthreads();
    for (int s = 128; s >= 1; s >>= 1) {
        if (tid < s) red[tid] += red[tid + s];
        __syncthreads();
    }
    if (tid == 0) {
        g_rmax[b * L_ + rrow] = M;
        g_rsumInv[b * L_ + rrow] = 1.0f / red[0];
    }
}

__global__ __launch_bounds__(256) void k_colstats() {
    const int b = blockIdx.y;
    const int jt = threadIdx.x & 31;
    const int isl = threadIdx.x >> 5;
    const int j = blockIdx.x * 32 + jt;
    const float* base = g_E + (size_t)b * L_ * L_ + j;

    float m = NEG_INF, s = 0.f;
    const int ibeg = isl * 256, iend = ibeg + 256;
    for (int i = ibeg; i < iend; i++) {
        float x = base[(size_t)i * L_];
        if (x <= m) {
            s += __expf(x - m);
        } else {
            s = s * __expf(m - x) + 1.f;
            m = x;
        }
    }
    __shared__ float ms[8][32], ss[8][32];
    ms[isl][jt] = m; ss[isl][jt] = s;
    __syncthreads();
    if (isl == 0) {
        float M = m, S = s;
        #pragma unroll
        for (int k = 1; k < 8; k++) {
            float mk = ms[k][jt], sk = ss[k][jt];
            if (mk <= M) {
                S += sk * __expf(mk - M);
            } else {
                S = S * __expf(M - mk) + sk;
                M = mk;
            }
        }
        g_cmax[b * L_ + j] = M;
        g_csumInv[b * L_ + j] = 1.0f / S;
    }
}

// ---------------------------------------------------------------------------
// Apply: P = tf32round(exp(E - rm) * ri), Q = tf32round(exp(E - cm) * ci).
// ---------------------------------------------------------------------------
__global__ __launch_bounds__(256) void k_apply() {
    const int b = blockIdx.y, i = blockIdx.x;
    const float* Erow = g_E + (size_t)(b * L_ + i) * L_;
    float* Prow = g_P + (size_t)(b * L_ + i) * L_;
    float* Qrow = g_Q + (size_t)(b * L_ + i) * L_;
    const float* cmv = g_cmax + b * L_;
    const float* civ = g_csumInv + b * L_;
    const float rm = g_rmax[b * L_ + i];
    const float ri = g_rsumInv[b * L_ + i];

    for (int j = threadIdx.x * 4; j < L_; j += 1024) {
        float4 e = *(const float4*)(Erow + j);
        float4 cm = *(const float4*)(cmv + j);
        float4 ci = *(const float4*)(civ + j);
        float4 p, qv;
        p.x = tf32r(__expf(e.x - rm) * ri);
        p.y = tf32r(__expf(e.y - rm) * ri);
        p.z = tf32r(__expf(e.z - rm) * ri);
        p.w = tf32r(__expf(e.w - rm) * ri);
        qv.x = tf32r(__expf(e.x - cm.x) * ci.x);
        qv.y = tf32r(__expf(e.y - cm.y) * ci.y);
        qv.z = tf32r(__expf(e.z - cm.z) * ci.z);
        qv.w = tf32r(__expf(e.w - cm.w) * ci.w);
        *(float4*)(Prow + j) = p;
        *(float4*)(Qrow + j) = qv;
    }
}

// ---------------------------------------------------------------------------
// a_tilda[i,d] = sum_j P[i,j]*Bt[j,d].  128x64 tile, 2 CTAs/SM, pure cp.async.
// Ps [m=i 128][k=j 32] pad 36; Bs [k=j 32][n=d 64] pad 72.
// Warps 4m x 2n: per warp m 2x16, n 4x8.
// ---------------------------------------------------------------------------
#define PPAD 36
#define PBUF (128 * PPAD)
#define NPAD2 72
#define NBUF2 (32 * NPAD2)
__global__ __launch_bounds__(256, 2) void k_atilda(float* __restrict__ out) {
    extern __shared__ float sm[];
    float* Ps = sm;                              // 2 * PBUF
    float* BH = sm + 2 * PBUF;                   // 2 * NBUF2
    const uint32_t uP = smem_u32(Ps), uB = smem_u32(BH);
    const int tid = threadIdx.x, lane = tid & 31, wid = tid >> 5;
    const int wm = wid & 3, wn = wid >> 2;
    const int q = lane >> 2, r = lane & 3;
    const int b = blockIdx.z, i0 = blockIdx.y * 128, d0 = blockIdx.x * 64;
    const float* Pb = g_P + (size_t)b * L_ * L_;
    const float* Btb = g_Bt + (size_t)b * L_ * D_ + d0;

    float acc[2][4][4];
    #pragma unroll
    for (int mt = 0; mt < 2; mt++)
        #pragma unroll
        for (int nt = 0; nt < 4; nt++)
            #pragma unroll
            for (int e = 0; e < 4; e++) acc[mt][nt][e] = 0.f;

    #define STAGE_P(c)                                                                  \
        do {                                                                            \
            const int _buf = (c) & 1, _j0 = (c) * 32;                                   \
            _Pragma("unroll")                                                           \
            for (int t = 0; t < 4; t++) {                                               \
                int idx = t * 256 + tid;                                                \
                int prow = idx >> 3, pch = idx & 7;                                     \
                cpa16(uP + (uint32_t)(_buf * PBUF + prow * PPAD + pch * 4) * 4u,        \
                      Pb + (size_t)(i0 + prow) * L_ + _j0 + pch * 4);                   \
            }                                                                           \
            _Pragma("unroll")                                                           \
            for (int t = 0; t < 2; t++) {                                               \
                int idx = t * 256 + tid;                                                \
                int brow = idx >> 4, bch = idx & 15;                                    \
                cpa16(uB + (uint32_t)(_buf * NBUF2 + brow * NPAD2 + bch * 4) * 4u,      \
                      Btb + (size_t)(_j0 + brow) * D_ + bch * 4);                       \
            }                                                                           \
            CP_COMMIT();                                                                \
        } while (0)

    STAGE_P(0);
    for (int c = 0; c < 64; c++) {
        const int buf = c & 1;
        if (c + 1 < 64) { STAGE_P(c + 1); CP_WAIT1(); }
        else            { CP_WAIT0(); }
        __syncthreads();
        const float* P_ = Ps + buf * PBUF;
        const float* BH_ = BH + buf * NBUF2;
        #pragma unroll
        for (int ks = 0; ks < 4; ks++) {
            const int kb = ks * 8;
            uint32_t pa[2][4], bh[4][2];
            #pragma unroll
            for (int mt = 0; mt < 2; mt++) {
                const int rb = wm * 32 + mt * 16;
                pa[mt][0] = __float_as_uint(P_[(rb + q) * PPAD + kb + r]);
                pa[mt][1] = __float_as_uint(P_[(rb + q + 8) * PPAD + kb + r]);
                pa[mt][2] = __float_as_uint(P_[(rb + q) * PPAD + kb + r + 4]);
                pa[mt][3] = __float_as_uint(P_[(rb + q + 8) * PPAD + kb + r + 4]);
            }
            #pragma unroll
            for (int nt = 0; nt < 4; nt++) {
                const int nb = wn * 32 + nt * 8;
                bh[nt][0] = __float_as_uint(BH_[(kb + r) * NPAD2 + nb + q]);
                bh[nt][1] = __float_as_uint(BH_[(kb + r + 4) * NPAD2 + nb + q]);
            }
            #pragma unroll
            for (int mt = 0; mt < 2; mt++)
                #pragma unroll
                for (int nt = 0; nt < 4; nt++)
                    mma8(acc[mt][nt], pa[mt], bh[nt]);
        }
        __syncthreads();
    }
    #undef STAGE_P

    float* Ob = out + ((size_t)b * L_ + i0) * D_ + d0;
    #pragma unroll
    for (int mt = 0; mt < 2; mt++)
        #pragma unroll
        for (int nt = 0; nt < 4; nt++) {
            int row = wm * 32 + mt * 16 + q;
            int col = wn * 32 + nt * 8 + r * 2;
            *(float2*)(Ob + (size_t)row * D_ + col) =
                make_float2(acc[mt][nt][0], acc[mt][nt][1]);
            *(float2*)(Ob + (size_t)(row + 8) * D_ + col) =
                make_float2(acc[mt][nt][2], acc[mt][nt][3]);
        }
}

// ---------------------------------------------------------------------------
// b_tilda[j,d] = sum_i Q[i,j]*At[i,d].  128x64 tile, 2 CTAs/SM, pure cp.async.
// Qs [k=i 32][m=j 128] pad 136; As [k=i 32][n=d 64] pad 72.
// ---------------------------------------------------------------------------
#define KNPAD 136
#define KNBUF (32 * KNPAD)
__global__ __launch_bounds__(256, 2) void k_btilda(float* __restrict__ out) {
    extern __shared__ float sm[];
    float* Qs = sm;                              // 2 * KNBUF
    float* AH = sm + 2 * KNBUF;                  // 2 * NBUF2
    const uint32_t uQ = smem_u32(Qs), uA = smem_u32(AH);
    const int tid = threadIdx.x, lane = tid & 31, wid = tid >> 5;
    const int wm = wid & 3, wn = wid >> 2;
    const int q = lane >> 2, r = lane & 3;
    const int b = blockIdx.z, j0 = blockIdx.y * 128, d0 = blockIdx.x * 64;
    const float* Qb = g_Q + (size_t)b * L_ * L_ + j0;
    const float* Atb = g_At + (size_t)b * L_ * D_ + d0;

    float acc[2][4][4];
    #pragma unroll
    for (int mt = 0; mt < 2; mt++)
        #pragma unroll
        for (int nt = 0; nt < 4; nt++)
            #pragma unroll
            for (int e = 0; e < 4; e++) acc[mt][nt][e] = 0.f;

    #define STAGE_Q(c)                                                                  \
        do {                                                                            \
            const int _buf = (c) & 1, _i0 = (c) * 32;                                   \
            _Pragma("unroll")                                                           \
            for (int t = 0; t < 4; t++) {                                               \
                int idx = t * 256 + tid;                                                \
                int row = idx >> 5, ch = idx & 31;                                      \
                cpa16(uQ + (uint32_t)(_buf * KNBUF + row * KNPAD + ch * 4) * 4u,        \
                      Qb + (size_t)(_i0 + row) * L_ + ch * 4);                          \
            }                                                                           \
            _Pragma("unroll")                                                           \
            for (int t = 0; t < 2; t++) {                                               \
                int idx = t * 256 + tid;                                                \
                int row = idx >> 4, ch = idx & 15;                                      \
                cpa16(uA + (uint32_t)(_buf * NBUF2 + row * NPAD2 + ch * 4) * 4u,        \
                      Atb + (size_t)(_i0 + row) * D_ + ch * 4);                         \
            }                                                                           \
            CP_COMMIT();                                                                \
        } while (0)

    STAGE_Q(0);
    for (int c = 0; c < 64; c++) {
        const int buf = c & 1;
        if (c + 1 < 64) { STAGE_Q(c + 1); CP_WAIT1(); }
        else            { CP_WAIT0(); }
        __syncthreads();
        const float* Q_ = Qs + buf * KNBUF;
        const float* AH_ = AH + buf * NBUF2;
        #pragma unroll
        for (int ks = 0; ks < 4; ks++) {
            const int kb = ks * 8;
            uint32_t qa[2][4], bh[4][2];
            #pragma unroll
            for (int mt = 0; mt < 2; mt++) {
                const int mb = wm * 32 + mt * 16;
                qa[mt][0] = __float_as_uint(Q_[(kb + r) * KNPAD + mb + q]);
                qa[mt][1] = __float_as_uint(Q_[(kb + r) * KNPAD + mb + q + 8]);
                qa[mt][2] = __float_as_uint(Q_[(kb + r + 4) * KNPAD + mb + q]);
                qa[mt][3] = __float_as_uint(Q_[(kb + r + 4) * KNPAD + mb + q + 8]);
            }
            #pragma unroll
            for (int nt = 0; nt < 4; nt++) {
                const int nb = wn * 32 + nt * 8;
                bh[nt][0] = __float_as_uint(AH_[(kb + r) * NPAD2 + nb + q]);
                bh[nt][1] = __float_as_uint(AH_[(kb + r + 4) * NPAD2 + nb + q]);
            }
            #pragma unroll
            for (int mt = 0; mt < 2; mt++)
                #pragma unroll
                for (int nt = 0; nt < 4; nt++)
                    mma8(acc[mt][nt], qa[mt], bh[nt]);
        }
        __syncthreads();
    }
    #undef STAGE_Q

    float* Ob = out + ((size_t)b * L_ + j0) * D_ + d0;
    #pragma unroll
    for (int mt = 0; mt < 2; mt++)
        #pragma unroll
        for (int nt = 0; nt < 4; nt++) {
            int row = wm * 32 + mt * 16 + q;
            int col = wn * 32 + nt * 8 + r * 2;
            *(float2*)(Ob + (size_t)row * D_ + col) =
                make_float2(acc[mt][nt][0], acc[mt][nt][1]);
            *(float2*)(Ob + (size_t)(row + 8) * D_ + col) =
                make_float2(acc[mt][nt][2], acc[mt][nt][3]);
        }
}

// ---------------------------------------------------------------------------
extern "C" void kernel_launch(void* const* d_in, const int* in_sizes, int n_in,
                              void* d_out, int out_size) {
    const float* A = (const float*)d_in[0];
    const float* B = (const float*)d_in[1];
    float* out = (float*)d_out;
    float* a_tilda = out;
    float* b_tilda = out + (size_t)BN_ * L_ * D_;

    const int SMEM_E = 8 * EB2 * 4;                             // 81920 B
    const int SMEM_A = (2 * PBUF + 2 * NBUF2) * 4;              // 55296 B
    const int SMEM_B = (2 * KNBUF + 2 * NBUF2) * 4;             // 53248 B
    cudaFuncSetAttribute(k_gemm_e, cudaFuncAttributeMaxDynamicSharedMemorySize, SMEM_E);
    cudaFuncSetAttribute(k_atilda, cudaFuncAttributeMaxDynamicSharedMemorySize, SMEM_A);
    cudaFuncSetAttribute(k_btilda, cudaFuncAttributeMaxDynamicSharedMemorySize, SMEM_B);

    k_round<<<(BN_ * L_ * D_) / 1024, 256>>>(A, B);
    k_gemm_e<<<dim3(L_ / 128, L_ / 128, BN_), 256, SMEM_E>>>(A, B);
    k_rowstats<<<dim3(L_, BN_), 256>>>();
    k_colstats<<<dim3(L_ / 32, BN_), 256>>>();
    k_apply<<<dim3(L_, BN_), 256>>>();
    k_atilda<<<dim3(D_ / 64, L_ / 128, BN_), 256, SMEM_A>>>(a_tilda);
    k_btilda<<<dim3(D_ / 64, L_ / 128, BN_), 256, SMEM_B>>>(b_tilda);
}

// round 14
// speedup vs baseline: 1.0336x; 1.0336x over previous
#include <cuda_runtime.h>
#include <math.h>
#include <stdint.h>

#define BN_ 8
#define L_ 2048
#define D_ 1024

// Scratch
__device__ float g_E[(size_t)BN_ * L_ * L_];
__device__ float g_P[(size_t)BN_ * L_ * L_];   // row-softmax(E), tf32-rounded
__device__ float g_Q[(size_t)BN_ * L_ * L_];   // col-softmax(E), tf32-rounded
__device__ float g_At[(size_t)BN_ * L_ * D_];  // tf32-rounded A
__device__ float g_Bt[(size_t)BN_ * L_ * D_];  // tf32-rounded B
__device__ float g_rmax[BN_ * L_];
__device__ float g_rsumInv[BN_ * L_];
__device__ float g_cmax[BN_ * L_];
__device__ float g_csumInv[BN_ * L_];

#define NEG_INF __int_as_float(0xff800000)

static __device__ __forceinline__ uint32_t smem_u32(const void* p) {
    uint32_t a;
    asm("{ .reg .u64 t; cvta.to.shared.u64 t, %1; cvt.u32.u64 %0, t; }"
        : "=r"(a) : "l"(p));
    return a;
}
static __device__ __forceinline__ uint32_t cvt_tf32(float x) {
    uint32_t h;
    asm("cvt.rna.tf32.f32 %0, %1;" : "=r"(h) : "f"(x));
    return h;
}
static __device__ __forceinline__ float tf32r(float x) {
    return __uint_as_float(cvt_tf32(x));
}
static __device__ __forceinline__ uint32_t bf2(float lo, float hi) {
    uint32_t d;
    asm("cvt.rn.bf16x2.f32 %0, %1, %2;" : "=r"(d) : "f"(hi), "f"(lo));
    return d;
}
static __device__ __forceinline__ float bflo(uint32_t p) { return __uint_as_float(p << 16); }
static __device__ __forceinline__ float bfhi(uint32_t p) { return __uint_as_float(p & 0xffff0000u); }

static __device__ __forceinline__ void mma8(float c[4], const uint32_t a[4],
                                            const uint32_t b[2]) {
    asm volatile(
        "mma.sync.aligned.m16n8k8.row.col.f32.tf32.tf32.f32 "
        "{%0,%1,%2,%3},{%4,%5,%6,%7},{%8,%9},{%0,%1,%2,%3};"
        : "+f"(c[0]), "+f"(c[1]), "+f"(c[2]), "+f"(c[3])
        : "r"(a[0]), "r"(a[1]), "r"(a[2]), "r"(a[3]), "r"(b[0]), "r"(b[1]));
}
static __device__ __forceinline__ void mma16(float c[4], const uint32_t a[4],
                                             const uint32_t b[2]) {
    asm volatile(
        "mma.sync.aligned.m16n8k16.row.col.f32.bf16.bf16.f32 "
        "{%0,%1,%2,%3},{%4,%5,%6,%7},{%8,%9},{%0,%1,%2,%3};"
        : "+f"(c[0]), "+f"(c[1]), "+f"(c[2]), "+f"(c[3])
        : "r"(a[0]), "r"(a[1]), "r"(a[2]), "r"(a[3]), "r"(b[0]), "r"(b[1]));
}
static __device__ __forceinline__ void cpa16(uint32_t dst, const void* src) {
    asm volatile("cp.async.cg.shared.global [%0], [%1], 16;" :: "r"(dst), "l"(src));
}
#define CP_COMMIT() asm volatile("cp.async.commit_group;" ::: "memory")
#define CP_WAIT1()  asm volatile("cp.async.wait_group 1;" ::: "memory")
#define CP_WAIT0()  asm volatile("cp.async.wait_group 0;" ::: "memory")

// ---------------------------------------------------------------------------
// Round A, B to tf32 once (for phase-2).
// ---------------------------------------------------------------------------
__global__ __launch_bounds__(256) void k_round(const float* __restrict__ A,
                                               const float* __restrict__ B) {
    const size_t i = ((size_t)blockIdx.x * 256 + threadIdx.x) * 4;
    float4 a = *(const float4*)(A + i);
    float4 b = *(const float4*)(B + i);
    a.x = tf32r(a.x); a.y = tf32r(a.y); a.z = tf32r(a.z); a.w = tf32r(a.w);
    b.x = tf32r(b.x); b.y = tf32r(b.y); b.z = tf32r(b.z); b.w = tf32r(b.w);
    *(float4*)(g_At + i) = a;
    *(float4*)(g_Bt + i) = b;
}

// ---------------------------------------------------------------------------
// E = A @ B^T via 3xBF16 (hh + hl + lh), m16n8k16. 128x128 tile, BK=32,
// 8 warps (4m x 2n), 256 thr.  Warp-parity-staggered ks order.
// ---------------------------------------------------------------------------
#define EP2 20
#define EB2 (128 * EP2)
__global__ __launch_bounds__(256, 1) void k_gemm_e(const float* __restrict__ A,
                                                   const float* __restrict__ B) {
    extern __shared__ uint32_t smu[];
    uint32_t* tAH = smu;
    uint32_t* tAL = smu + 2 * EB2;
    uint32_t* tBH = smu + 4 * EB2;
    uint32_t* tBL = smu + 6 * EB2;
    const int tid = threadIdx.x, lane = tid & 31, wid = tid >> 5;
    const int wm = wid & 3, wn = wid >> 2;
    const int q = lane >> 2, r = lane & 3;
    const int par = wid & 1;
    const int b = blockIdx.z, i0 = blockIdx.y * 128, j0 = blockIdx.x * 128;
    const float* Ab = A + ((size_t)b * L_ + i0) * D_;
    const float* Bb = B + ((size_t)b * L_ + j0) * D_;

    float acc[2][8][4];
    #pragma unroll
    for (int mt = 0; mt < 2; mt++)
        #pragma unroll
        for (int nt = 0; nt < 8; nt++)
            #pragma unroll
            for (int e = 0; e < 4; e++) acc[mt][nt][e] = 0.f;

    const int srow = tid >> 2;
    const int sc4 = tid & 3;

    float4 av[2][2], bv[2][2];
    #define LOADREGS_E(c)                                                              \
        do {                                                                           \
            const int _k0 = (c) * 32 + sc4 * 8;                                        \
            _Pragma("unroll")                                                          \
            for (int t = 0; t < 2; t++) {                                              \
                int row = t * 64 + srow;                                               \
                av[t][0] = *(const float4*)(Ab + (size_t)row * D_ + _k0);              \
                av[t][1] = *(const float4*)(Ab + (size_t)row * D_ + _k0 + 4);          \
                bv[t][0] = *(const float4*)(Bb + (size_t)row * D_ + _k0);              \
                bv[t][1] = *(const float4*)(Bb + (size_t)row * D_ + _k0 + 4);          \
            }                                                                          \
        } while (0)
    #define PACKSTORE(dstH, dstL, v0, v1, off)                                          \
        do {                                                                            \
            uint32_t h0 = bf2((v0).x, (v0).y), h1 = bf2((v0).z, (v0).w);                \
            uint32_t h2 = bf2((v1).x, (v1).y), h3 = bf2((v1).z, (v1).w);                \
            uint32_t l0 = bf2((v0).x - bflo(h0), (v0).y - bfhi(h0));                    \
            uint32_t l1 = bf2((v0).z - bflo(h1), (v0).w - bfhi(h1));                    \
            uint32_t l2 = bf2((v1).x - bflo(h2), (v1).y - bfhi(h2));                    \
            uint32_t l3 = bf2((v1).z - bflo(h3), (v1).w - bfhi(h3));                    \
            *(uint4*)((dstH) + (off)) = make_uint4(h0, h1, h2, h3);                     \
            *(uint4*)((dstL) + (off)) = make_uint4(l0, l1, l2, l3);                     \
        } while (0)
    #define STAGE_E(bufn)                                                              \
        do {                                                                           \
            _Pragma("unroll")                                                          \
            for (int t = 0; t < 2; t++) {                                              \
                int row = t * 64 + srow;                                               \
                int off = (bufn) * EB2 + row * EP2 + sc4 * 4;                          \
                PACKSTORE(tAH, tAL, av[t][0], av[t][1], off);                          \
                PACKSTORE(tBH, tBL, bv[t][0], bv[t][1], off);                          \
            }                                                                          \
        } while (0)

    LOADREGS_E(0);
    for (int c = 0; c < 32; c++) {
        const int buf = c & 1;
        STAGE_E(buf);
        if (c + 1 < 32) LOADREGS_E(c + 1);
        __syncthreads();
        const uint32_t* AH_ = tAH + buf * EB2;
        const uint32_t* AL_ = tAL + buf * EB2;
        const uint32_t* BH_ = tBH + buf * EB2;
        const uint32_t* BL_ = tBL + buf * EB2;
        #pragma unroll
        for (int ks = 0; ks < 2; ks++) {
            const int kb2 = (ks ^ par) * 8;          // staggered per warp parity
            uint32_t ah[2][4], al[2][4], bh[8][2], bl[8][2];
            #pragma unroll
            for (int mt = 0; mt < 2; mt++) {
                const int rb = wm * 32 + mt * 16;
                ah[mt][0] = AH_[(rb + q) * EP2 + kb2 + r];
                ah[mt][1] = AH_[(rb + q + 8) * EP2 + kb2 + r];
                ah[mt][2] = AH_[(rb + q) * EP2 + kb2 + r + 4];
                ah[mt][3] = AH_[(rb + q + 8) * EP2 + kb2 + r + 4];
                al[mt][0] = AL_[(rb + q) * EP2 + kb2 + r];
                al[mt][1] = AL_[(rb + q + 8) * EP2 + kb2 + r];
                al[mt][2] = AL_[(rb + q) * EP2 + kb2 + r + 4];
                al[mt][3] = AL_[(rb + q + 8) * EP2 + kb2 + r + 4];
            }
            #pragma unroll
            for (int nt = 0; nt < 8; nt++) {
                const int nb = wn * 64 + nt * 8;
                bh[nt][0] = BH_[(nb + q) * EP2 + kb2 + r];
                bh[nt][1] = BH_[(nb + q) * EP2 + kb2 + r + 4];
                bl[nt][0] = BL_[(nb + q) * EP2 + kb2 + r];
                bl[nt][1] = BL_[(nb + q) * EP2 + kb2 + r + 4];
            }
            #pragma unroll
            for (int mt = 0; mt < 2; mt++)
                #pragma unroll
                for (int nt = 0; nt < 8; nt++) {
                    mma16(acc[mt][nt], al[mt], bh[nt]);
                    mma16(acc[mt][nt], ah[mt], bl[nt]);
                    mma16(acc[mt][nt], ah[mt], bh[nt]);
                }
        }
        __syncthreads();
    }
    #undef STAGE_E
    #undef PACKSTORE
    #undef LOADREGS_E

    float* Eb = g_E + ((size_t)b * L_ + i0) * L_ + j0;
    #pragma unroll
    for (int mt = 0; mt < 2; mt++)
        #pragma unroll
        for (int nt = 0; nt < 8; nt++) {
            int row = wm * 32 + mt * 16 + q;
            int col = wn * 64 + nt * 8 + r * 2;
            *(float2*)(Eb + (size_t)row * L_ + col) =
                make_float2(acc[mt][nt][0], acc[mt][nt][1]);
            *(float2*)(Eb + (size_t)(row + 8) * L_ + col) =
                make_float2(acc[mt][nt][2], acc[mt][nt][3]);
        }
}

// ---------------------------------------------------------------------------
// Row / col softmax stats
// ---------------------------------------------------------------------------
__global__ __launch_bounds__(256) void k_rowstats() {
    const int b = blockIdx.y, rrow = blockIdx.x;
    const float* row = g_E + (size_t)(b * L_ + rrow) * L_;
    const int tid = threadIdx.x;
    __shared__ float red[256];

    float m = NEG_INF;
    for (int j = tid * 4; j < L_; j += 1024) {
        float4 v = *(const float4*)(row + j);
        m = fmaxf(m, fmaxf(fmaxf(v.x, v.y), fmaxf(v.z, v.w)));
    }
    red[tid] = m; __syncthreads();
    for (int s = 128; s >= 1; s >>= 1) {
        if (tid < s) red[tid] = fmaxf(red[tid], red[tid + s]);
        __syncthreads();
    }
    const float M = red[0];
    __syncthreads();

    float sum = 0.f;
    for (int j = tid * 4; j < L_; j += 1024) {
        float4 v = *(const float4*)(row + j);
        sum += __expf(v.x - M) + __expf(v.y - M) + __expf(v.z - M) + __expf(v.w - M);
    }
    red[tid] = sum; __syncthreads();
    for (int s = 128; s >= 1; s >>= 1) {
        if (tid < s) red[tid] += red[tid + s];
        __syncthreads();
    }
    if (tid == 0) {
        g_rmax[b * L_ + rrow] = M;
        g_rsumInv[b * L_ + rrow] = 1.0f / red[0];
    }
}

__global__ __launch_bounds__(256) void k_colstats() {
    const int b = blockIdx.y;
    const int jt = threadIdx.x & 31;
    const int isl = threadIdx.x >> 5;
    const int j = blockIdx.x * 32 + jt;
    const float* base = g_E + (size_t)b * L_ * L_ + j;

    float m = NEG_INF, s = 0.f;
    const int ibeg = isl * 256, iend = ibeg + 256;
    for (int i = ibeg; i < iend; i++) {
        float x = base[(size_t)i * L_];
        if (x <= m) {
            s += __expf(x - m);
        } else {
            s = s * __expf(m - x) + 1.f;
            m = x;
        }
    }
    __shared__ float ms[8][32], ss[8][32];
    ms[isl][jt] = m; ss[isl][jt] = s;
    __syncthreads();
    if (isl == 0) {
        float M = m, S = s;
        #pragma unroll
        for (int k = 1; k < 8; k++) {
            float mk = ms[k][jt], sk = ss[k][jt];
            if (mk <= M) {
                S += sk * __expf(mk - M);
            } else {
                S = S * __expf(M - mk) + sk;
                M = mk;
            }
        }
        g_cmax[b * L_ + j] = M;
        g_csumInv[b * L_ + j] = 1.0f / S;
    }
}

// ---------------------------------------------------------------------------
// Apply: P = tf32round(exp(E - rm) * ri), Q = tf32round(exp(E - cm) * ci).
// ---------------------------------------------------------------------------
__global__ __launch_bounds__(256) void k_apply() {
    const int b = blockIdx.y, i = blockIdx.x;
    const float* Erow = g_E + (size_t)(b * L_ + i) * L_;
    float* Prow = g_P + (size_t)(b * L_ + i) * L_;
    float* Qrow = g_Q + (size_t)(b * L_ + i) * L_;
    const float* cmv = g_cmax + b * L_;
    const float* civ = g_csumInv + b * L_;
    const float rm = g_rmax[b * L_ + i];
    const float ri = g_rsumInv[b * L_ + i];

    for (int j = threadIdx.x * 4; j < L_; j += 1024) {
        float4 e = *(const float4*)(Erow + j);
        float4 cm = *(const float4*)(cmv + j);
        float4 ci = *(const float4*)(civ + j);
        float4 p, qv;
        p.x = tf32r(__expf(e.x - rm) * ri);
        p.y = tf32r(__expf(e.y - rm) * ri);
        p.z = tf32r(__expf(e.z - rm) * ri);
        p.w = tf32r(__expf(e.w - rm) * ri);
        qv.x = tf32r(__expf(e.x - cm.x) * ci.x);
        qv.y = tf32r(__expf(e.y - cm.y) * ci.y);
        qv.z = tf32r(__expf(e.z - cm.z) * ci.z);
        qv.w = tf32r(__expf(e.w - cm.w) * ci.w);
        *(float4*)(Prow + j) = p;
        *(float4*)(Qrow + j) = qv;
    }
}

// ---------------------------------------------------------------------------
// a_tilda[i,d] = sum_j P[i,j]*Bt[j,d].  Pure cp.async staging, 128x128 tile,
// warp-parity-staggered ks order.
// ---------------------------------------------------------------------------
#define PPAD 36
#define PBUF (128 * PPAD)
#define KNPAD 136
#define KNBUF (32 * KNPAD)
__global__ __launch_bounds__(256, 1) void k_atilda(float* __restrict__ out) {
    extern __shared__ float sm[];
    float* Ps = sm;
    float* BH = sm + 2 * PBUF;
    const uint32_t uP = smem_u32(Ps), uB = smem_u32(BH);
    const int tid = threadIdx.x, lane = tid & 31, wid = tid >> 5;
    const int wm = wid & 3, wn = wid >> 2;
    const int q = lane >> 2, r = lane & 3;
    const int par2 = (wid & 1) << 1;
    const int b = blockIdx.z, i0 = blockIdx.y * 128, d0 = blockIdx.x * 128;
    const float* Pb = g_P + (size_t)b * L_ * L_;
    const float* Btb = g_Bt + (size_t)b * L_ * D_ + d0;

    float acc[2][8][4];
    #pragma unroll
    for (int mt = 0; mt < 2; mt++)
        #pragma unroll
        for (int nt = 0; nt < 8; nt++)
            #pragma unroll
            for (int e = 0; e < 4; e++) acc[mt][nt][e] = 0.f;

    #define STAGE_P(c)                                                                  \
        do {                                                                            \
            const int _buf = (c) & 1, _j0 = (c) * 32;                                   \
            _Pragma("unroll")                                                           \
            for (int t = 0; t < 4; t++) {                                               \
                int idx = t * 256 + tid;                                                \
                int prow = idx >> 3, pch = idx & 7;                                     \
                cpa16(uP + (uint32_t)(_buf * PBUF + prow * PPAD + pch * 4) * 4u,        \
                      Pb + (size_t)(i0 + prow) * L_ + _j0 + pch * 4);                   \
                int brow = idx >> 5, bch = idx & 31;                                    \
                cpa16(uB + (uint32_t)(_buf * KNBUF + brow * KNPAD + bch * 4) * 4u,      \
                      Btb + (size_t)(_j0 + brow) * D_ + bch * 4);                       \
            }                                                                           \
            CP_COMMIT();                                                                \
        } while (0)

    STAGE_P(0);
    for (int c = 0; c < 64; c++) {
        const int buf = c & 1;
        if (c + 1 < 64) { STAGE_P(c + 1); CP_WAIT1(); }
        else            { CP_WAIT0(); }
        __syncthreads();
        const float* P_ = Ps + buf * PBUF;
        const float* BH_ = BH + buf * KNBUF;
        #pragma unroll
        for (int ks = 0; ks < 4; ks++) {
            const int kb = ((ks + par2) & 3) * 8;   // staggered per warp parity
            uint32_t pa[2][4], bh[8][2];
            #pragma unroll
            for (int mt = 0; mt < 2; mt++) {
                const int rb = wm * 32 + mt * 16;
                pa[mt][0] = __float_as_uint(P_[(rb + q) * PPAD + kb + r]);
                pa[mt][1] = __float_as_uint(P_[(rb + q + 8) * PPAD + kb + r]);
                pa[mt][2] = __float_as_uint(P_[(rb + q) * PPAD + kb + r + 4]);
                pa[mt][3] = __float_as_uint(P_[(rb + q + 8) * PPAD + kb + r + 4]);
            }
            #pragma unroll
            for (int nt = 0; nt < 8; nt++) {
                const int nb = wn * 64 + nt * 8;
                bh[nt][0] = __float_as_uint(BH_[(kb + r) * KNPAD + nb + q]);
                bh[nt][1] = __float_as_uint(BH_[(kb + r + 4) * KNPAD + nb + q]);
            }
            #pragma unroll
            for (int mt = 0; mt < 2; mt++)
                #pragma unroll
                for (int nt = 0; nt < 8; nt++)
                    mma8(acc[mt][nt], pa[mt], bh[nt]);
        }
        __syncthreads();
    }
    #undef STAGE_P

    float* Ob = out + ((size_t)b * L_ + i0) * D_ + d0;
    #pragma unroll
    for (int mt = 0; mt < 2; mt++)
        #pragma unroll
        for (int nt = 0; nt < 8; nt++) {
            int row = wm * 32 + mt * 16 + q;
            int col = wn * 64 + nt * 8 + r * 2;
            *(float2*)(Ob + (size_t)row * D_ + col) =
                make_float2(acc[mt][nt][0], acc[mt][nt][1]);
            *(float2*)(Ob + (size_t)(row + 8) * D_ + col) =
                make_float2(acc[mt][nt][2], acc[mt][nt][3]);
        }
}

// ---------------------------------------------------------------------------
// b_tilda[j,d] = sum_i Q[i,j]*At[i,d].  Pure cp.async staging, staggered ks.
// ---------------------------------------------------------------------------
__global__ __launch_bounds__(256, 1) void k_btilda(float* __restrict__ out) {
    extern __shared__ float sm[];
    float* Qs = sm;
    float* AH = sm + 2 * KNBUF;
    const uint32_t uQ = smem_u32(Qs), uA = smem_u32(AH);
    const int tid = threadIdx.x, lane = tid & 31, wid = tid >> 5;
    const int wm = wid & 3, wn = wid >> 2;
    const int q = lane >> 2, r = lane & 3;
    const int par2 = (wid & 1) << 1;
    const int b = blockIdx.z, j0 = blockIdx.y * 128, d0 = blockIdx.x * 128;
    const float* Qb = g_Q + (size_t)b * L_ * L_ + j0;
    const float* Atb = g_At + (size_t)b * L_ * D_ + d0;

    float acc[2][8][4];
    #pragma unroll
    for (int mt = 0; mt < 2; mt++)
        #pragma unroll
        for (int nt = 0; nt < 8; nt++)
            #pragma unroll
            for (int e = 0; e < 4; e++) acc[mt][nt][e] = 0.f;

    #define STAGE_Q(c)                                                                  \
        do {                                                                            \
            const int _buf = (c) & 1, _i0 = (c) * 32;                                   \
            _Pragma("unroll")                                                           \
            for (int t = 0; t < 4; t++) {                                               \
                int idx = t * 256 + tid;                                                \
                int row = idx >> 5, ch = idx & 31;                                      \
                cpa16(uQ + (uint32_t)(_buf * KNBUF + row * KNPAD + ch * 4) * 4u,        \
                      Qb + (size_t)(_i0 + row) * L_ + ch * 4);                          \
                cpa16(uA + (uint32_t)(_buf * KNBUF + row * KNPAD + ch * 4) * 4u,        \
                      Atb + (size_t)(_i0 + row) * D_ + ch * 4);                         \
            }                                                                           \
            CP_COMMIT();                                                                \
        } while (0)

    STAGE_Q(0);
    for (int c = 0; c < 64; c++) {
        const int buf = c & 1;
        if (c + 1 < 64) { STAGE_Q(c + 1); CP_WAIT1(); }
        else            { CP_WAIT0(); }
        __syncthreads();
        const float* Q_ = Qs + buf * KNBUF;
        const float* AH_ = AH + buf * KNBUF;
        #pragma unroll
        for (int ks = 0; ks < 4; ks++) {
            const int kb = ((ks + par2) & 3) * 8;   // staggered per warp parity
            uint32_t qa[2][4], bh[8][2];
            #pragma unroll
            for (int mt = 0; mt < 2; mt++) {
                const int mb = wm * 32 + mt * 16;
                qa[mt][0] = __float_as_uint(Q_[(kb + r) * KNPAD + mb + q]);
                qa[mt][1] = __float_as_uint(Q_[(kb + r) * KNPAD + mb + q + 8]);
                qa[mt][2] = __float_as_uint(Q_[(kb + r + 4) * KNPAD + mb + q]);
                qa[mt][3] = __float_as_uint(Q_[(kb + r + 4) * KNPAD + mb + q + 8]);
            }
            #pragma unroll
            for (int nt = 0; nt < 8; nt++) {
                const int nb = wn * 64 + nt * 8;
                bh[nt][0] = __float_as_uint(AH_[(kb + r) * KNPAD + nb + q]);
                bh[nt][1] = __float_as_uint(AH_[(kb + r + 4) * KNPAD + nb + q]);
            }
            #pragma unroll
            for (int mt = 0; mt < 2; mt++)
                #pragma unroll
                for (int nt = 0; nt < 8; nt++)
                    mma8(acc[mt][nt], qa[mt], bh[nt]);
        }
        __syncthreads();
    }
    #undef STAGE_Q

    float* Ob = out + ((size_t)b * L_ + j0) * D_ + d0;
    #pragma unroll
    for (int mt = 0; mt < 2; mt++)
        #pragma unroll
        for (int nt = 0; nt < 8; nt++) {
            int row = wm * 32 + mt * 16 + q;
            int col = wn * 64 + nt * 8 + r * 2;
            *(float2*)(Ob + (size_t)row * D_ + col) =
                make_float2(acc[mt][nt][0], acc[mt][nt][1]);
            *(float2*)(Ob + (size_t)(row + 8) * D_ + col) =
                make_float2(acc[mt][nt][2], acc[mt][nt][3]);
        }
}

// ---------------------------------------------------------------------------
extern "C" void kernel_launch(void* const* d_in, const int* in_sizes, int n_in,
                              void* d_out, int out_size) {
    const float* A = (const float*)d_in[0];
    const float* B = (const float*)d_in[1];
    float* out = (float*)d_out;
    float* a_tilda = out;
    float* b_tilda = out + (size_t)BN_ * L_ * D_;

    const int SMEM_E = 8 * EB2 * 4;                             // 81920 B
    const int SMEM_A = (2 * PBUF + 2 * KNBUF) * 4;              // 71680 B
    const int SMEM_B = (4 * KNBUF) * 4;                         // 69632 B
    cudaFuncSetAttribute(k_gemm_e, cudaFuncAttributeMaxDynamicSharedMemorySize, SMEM_E);
    cudaFuncSetAttribute(k_atilda, cudaFuncAttributeMaxDynamicSharedMemorySize, SMEM_A);
    cudaFuncSetAttribute(k_btilda, cudaFuncAttributeMaxDynamicSharedMemorySize, SMEM_B);

    k_round<<<(BN_ * L_ * D_) / 1024, 256>>>(A, B);
    k_gemm_e<<<dim3(L_ / 128, L_ / 128, BN_), 256, SMEM_E>>>(A, B);
    k_rowstats<<<dim3(L_, BN_), 256>>>();
    k_colstats<<<dim3(L_ / 32, BN_), 256>>>();
    k_apply<<<dim3(L_, BN_), 256>>>();
    k_atilda<<<dim3(D_ / 128, L_ / 128, BN_), 256, SMEM_A>>>(a_tilda);
    k_btilda<<<dim3(D_ / 128, L_ / 128, BN_), 256, SMEM_B>>>(b_tilda);
}

// round 16
// speedup vs baseline: 1.1412x; 1.1041x over previous
#include <cuda_runtime.h>
#include <math.h>
#include <stdint.h>

#define BN_ 8
#define L_ 2048
#define D_ 1024

// Scratch
__device__ float g_E[(size_t)BN_ * L_ * L_];
__device__ float g_P[(size_t)BN_ * L_ * L_];   // row-softmax(E), tf32-rounded
__device__ float g_Q[(size_t)BN_ * L_ * L_];   // col-softmax(E), tf32-rounded
__device__ float g_At[(size_t)BN_ * L_ * D_];  // tf32-rounded A
__device__ float g_Bt[(size_t)BN_ * L_ * D_];  // tf32-rounded B
__device__ float g_rmax[BN_ * L_];
__device__ float g_rsumInv[BN_ * L_];
__device__ float g_cmax[BN_ * L_];
__device__ float g_csumInv[BN_ * L_];

#define NEG_INF __int_as_float(0xff800000)

static __device__ __forceinline__ uint32_t smem_u32(const void* p) {
    uint32_t a;
    asm("{ .reg .u64 t; cvta.to.shared.u64 t, %1; cvt.u32.u64 %0, t; }"
        : "=r"(a) : "l"(p));
    return a;
}
static __device__ __forceinline__ uint32_t cvt_tf32(float x) {
    uint32_t h;
    asm("cvt.rna.tf32.f32 %0, %1;" : "=r"(h) : "f"(x));
    return h;
}
static __device__ __forceinline__ float tf32r(float x) {
    return __uint_as_float(cvt_tf32(x));
}
static __device__ __forceinline__ uint32_t bf2(float lo, float hi) {
    uint32_t d;
    asm("cvt.rn.bf16x2.f32 %0, %1, %2;" : "=r"(d) : "f"(hi), "f"(lo));
    return d;
}
static __device__ __forceinline__ float bflo(uint32_t p) { return __uint_as_float(p << 16); }
static __device__ __forceinline__ float bfhi(uint32_t p) { return __uint_as_float(p & 0xffff0000u); }

static __device__ __forceinline__ void mma8(float c[4], const uint32_t a[4],
                                            const uint32_t b[2]) {
    asm volatile(
        "mma.sync.aligned.m16n8k8.row.col.f32.tf32.tf32.f32 "
        "{%0,%1,%2,%3},{%4,%5,%6,%7},{%8,%9},{%0,%1,%2,%3};"
        : "+f"(c[0]), "+f"(c[1]), "+f"(c[2]), "+f"(c[3])
        : "r"(a[0]), "r"(a[1]), "r"(a[2]), "r"(a[3]), "r"(b[0]), "r"(b[1]));
}
static __device__ __forceinline__ void mma16(float c[4], const uint32_t a[4],
                                             const uint32_t b[2]) {
    asm volatile(
        "mma.sync.aligned.m16n8k16.row.col.f32.bf16.bf16.f32 "
        "{%0,%1,%2,%3},{%4,%5,%6,%7},{%8,%9},{%0,%1,%2,%3};"
        : "+f"(c[0]), "+f"(c[1]), "+f"(c[2]), "+f"(c[3])
        : "r"(a[0]), "r"(a[1]), "r"(a[2]), "r"(a[3]), "r"(b[0]), "r"(b[1]));
}
static __device__ __forceinline__ void cpa16(uint32_t dst, const void* src) {
    asm volatile("cp.async.cg.shared.global [%0], [%1], 16;" :: "r"(dst), "l"(src));
}
#define CP_COMMIT() asm volatile("cp.async.commit_group;" ::: "memory")
#define CP_WAIT1()  asm volatile("cp.async.wait_group 1;" ::: "memory")
#define CP_WAIT0()  asm volatile("cp.async.wait_group 0;" ::: "memory")

// ---------------------------------------------------------------------------
// Round A, B to tf32 once (for phase-2).
// ---------------------------------------------------------------------------
__global__ __launch_bounds__(256) void k_round(const float* __restrict__ A,
                                               const float* __restrict__ B) {
    const size_t i = ((size_t)blockIdx.x * 256 + threadIdx.x) * 4;
    float4 a = *(const float4*)(A + i);
    float4 b = *(const float4*)(B + i);
    a.x = tf32r(a.x); a.y = tf32r(a.y); a.z = tf32r(a.z); a.w = tf32r(a.w);
    b.x = tf32r(b.x); b.y = tf32r(b.y); b.z = tf32r(b.z); b.w = tf32r(b.w);
    *(float4*)(g_At + i) = a;
    *(float4*)(g_Bt + i) = b;
}

// ---------------------------------------------------------------------------
// E = A @ B^T via 3xBF16 (hh + hl + lh), m16n8k16. 128x128 tile, BK=32,
// 8 warps (4m x 2n), 256 thr.  (R11 form.)
// ---------------------------------------------------------------------------
#define EP2 20
#define EB2 (128 * EP2)
__global__ __launch_bounds__(256, 1) void k_gemm_e(const float* __restrict__ A,
                                                   const float* __restrict__ B) {
    extern __shared__ uint32_t smu[];
    uint32_t* tAH = smu;
    uint32_t* tAL = smu + 2 * EB2;
    uint32_t* tBH = smu + 4 * EB2;
    uint32_t* tBL = smu + 6 * EB2;
    const int tid = threadIdx.x, lane = tid & 31, wid = tid >> 5;
    const int wm = wid & 3, wn = wid >> 2;
    const int q = lane >> 2, r = lane & 3;
    const int b = blockIdx.z, i0 = blockIdx.y * 128, j0 = blockIdx.x * 128;
    const float* Ab = A + ((size_t)b * L_ + i0) * D_;
    const float* Bb = B + ((size_t)b * L_ + j0) * D_;

    float acc[2][8][4];
    #pragma unroll
    for (int mt = 0; mt < 2; mt++)
        #pragma unroll
        for (int nt = 0; nt < 8; nt++)
            #pragma unroll
            for (int e = 0; e < 4; e++) acc[mt][nt][e] = 0.f;

    const int srow = tid >> 2;
    const int sc4 = tid & 3;

    float4 av[2][2], bv[2][2];
    #define LOADREGS_E(c)                                                              \
        do {                                                                           \
            const int _k0 = (c) * 32 + sc4 * 8;                                        \
            _Pragma("unroll")                                                          \
            for (int t = 0; t < 2; t++) {                                              \
                int row = t * 64 + srow;                                               \
                av[t][0] = *(const float4*)(Ab + (size_t)row * D_ + _k0);              \
                av[t][1] = *(const float4*)(Ab + (size_t)row * D_ + _k0 + 4);          \
                bv[t][0] = *(const float4*)(Bb + (size_t)row * D_ + _k0);              \
                bv[t][1] = *(const float4*)(Bb + (size_t)row * D_ + _k0 + 4);          \
            }                                                                          \
        } while (0)
    #define PACKSTORE(dstH, dstL, v0, v1, off)                                          \
        do {                                                                            \
            uint32_t h0 = bf2((v0).x, (v0).y), h1 = bf2((v0).z, (v0).w);                \
            uint32_t h2 = bf2((v1).x, (v1).y), h3 = bf2((v1).z, (v1).w);                \
            uint32_t l0 = bf2((v0).x - bflo(h0), (v0).y - bfhi(h0));                    \
            uint32_t l1 = bf2((v0).z - bflo(h1), (v0).w - bfhi(h1));                    \
            uint32_t l2 = bf2((v1).x - bflo(h2), (v1).y - bfhi(h2));                    \
            uint32_t l3 = bf2((v1).z - bflo(h3), (v1).w - bfhi(h3));                    \
            *(uint4*)((dstH) + (off)) = make_uint4(h0, h1, h2, h3);                     \
            *(uint4*)((dstL) + (off)) = make_uint4(l0, l1, l2, l3);                     \
        } while (0)
    #define STAGE_E(bufn)                                                              \
        do {                                                                           \
            _Pragma("unroll")                                                          \
            for (int t = 0; t < 2; t++) {                                              \
                int row = t * 64 + srow;                                               \
                int off = (bufn) * EB2 + row * EP2 + sc4 * 4;                          \
                PACKSTORE(tAH, tAL, av[t][0], av[t][1], off);                          \
                PACKSTORE(tBH, tBL, bv[t][0], bv[t][1], off);                          \
            }                                                                          \
        } while (0)

    LOADREGS_E(0);
    for (int c = 0; c < 32; c++) {
        const int buf = c & 1;
        STAGE_E(buf);
        if (c + 1 < 32) LOADREGS_E(c + 1);
        __syncthreads();
        const uint32_t* AH_ = tAH + buf * EB2;
        const uint32_t* AL_ = tAL + buf * EB2;
        const uint32_t* BH_ = tBH + buf * EB2;
        const uint32_t* BL_ = tBL + buf * EB2;
        #pragma unroll
        for (int ks = 0; ks < 2; ks++) {
            const int kb2 = ks * 8;
            uint32_t ah[2][4], al[2][4], bh[8][2], bl[8][2];
            #pragma unroll
            for (int mt = 0; mt < 2; mt++) {
                const int rb = wm * 32 + mt * 16;
                ah[mt][0] = AH_[(rb + q) * EP2 + kb2 + r];
                ah[mt][1] = AH_[(rb + q + 8) * EP2 + kb2 + r];
                ah[mt][2] = AH_[(rb + q) * EP2 + kb2 + r + 4];
                ah[mt][3] = AH_[(rb + q + 8) * EP2 + kb2 + r + 4];
                al[mt][0] = AL_[(rb + q) * EP2 + kb2 + r];
                al[mt][1] = AL_[(rb + q + 8) * EP2 + kb2 + r];
                al[mt][2] = AL_[(rb + q) * EP2 + kb2 + r + 4];
                al[mt][3] = AL_[(rb + q + 8) * EP2 + kb2 + r + 4];
            }
            #pragma unroll
            for (int nt = 0; nt < 8; nt++) {
                const int nb = wn * 64 + nt * 8;
                bh[nt][0] = BH_[(nb + q) * EP2 + kb2 + r];
                bh[nt][1] = BH_[(nb + q) * EP2 + kb2 + r + 4];
                bl[nt][0] = BL_[(nb + q) * EP2 + kb2 + r];
                bl[nt][1] = BL_[(nb + q) * EP2 + kb2 + r + 4];
            }
            #pragma unroll
            for (int mt = 0; mt < 2; mt++)
                #pragma unroll
                for (int nt = 0; nt < 8; nt++) {
                    mma16(acc[mt][nt], al[mt], bh[nt]);
                    mma16(acc[mt][nt], ah[mt], bl[nt]);
                    mma16(acc[mt][nt], ah[mt], bh[nt]);
                }
        }
        __syncthreads();
    }
    #undef STAGE_E
    #undef PACKSTORE
    #undef LOADREGS_E

    float* Eb = g_E + ((size_t)b * L_ + i0) * L_ + j0;
    #pragma unroll
    for (int mt = 0; mt < 2; mt++)
        #pragma unroll
        for (int nt = 0; nt < 8; nt++) {
            int row = wm * 32 + mt * 16 + q;
            int col = wn * 64 + nt * 8 + r * 2;
            *(float2*)(Eb + (size_t)row * L_ + col) =
                make_float2(acc[mt][nt][0], acc[mt][nt][1]);
            *(float2*)(Eb + (size_t)(row + 8) * L_ + col) =
                make_float2(acc[mt][nt][2], acc[mt][nt][3]);
        }
}

// ---------------------------------------------------------------------------
// Row / col softmax stats
// ---------------------------------------------------------------------------
__global__ __launch_bounds__(256) void k_rowstats() {
    const int b = blockIdx.y, rrow = blockIdx.x;
    const float* row = g_E + (size_t)(b * L_ + rrow) * L_;
    const int tid = threadIdx.x;
    __shared__ float red[256];

    float m = NEG_INF;
    for (int j = tid * 4; j < L_; j += 1024) {
        float4 v = *(const float4*)(row + j);
        m = fmaxf(m, fmaxf(fmaxf(v.x, v.y), fmaxf(v.z, v.w)));
    }
    red[tid] = m; __syncthreads();
    for (int s = 128; s >= 1; s >>= 1) {
        if (tid < s) red[tid] = fmaxf(red[tid], red[tid + s]);
        __syncthreads();
    }
    const float M = red[0];
    __syncthreads();

    float sum = 0.f;
    for (int j = tid * 4; j < L_; j += 1024) {
        float4 v = *(const float4*)(row + j);
        sum += __expf(v.x - M) + __expf(v.y - M) + __expf(v.z - M) + __expf(v.w - M);
    }
    red[tid] = sum; __syncthreads();
    for (int s = 128; s >= 1; s >>= 1) {
        if (tid < s) red[tid] += red[tid + s];
        __syncthreads();
    }
    if (tid == 0) {
        g_rmax[b * L_ + rrow] = M;
        g_rsumInv[b * L_ + rrow] = 1.0f / red[0];
    }
}

__global__ __launch_bounds__(256) void k_colstats() {
    const int b = blockIdx.y;
    const int jt = threadIdx.x & 31;
    const int isl = threadIdx.x >> 5;
    const int j = blockIdx.x * 32 + jt;
    const float* base = g_E + (size_t)b * L_ * L_ + j;

    float m = NEG_INF, s = 0.f;
    const int ibeg = isl * 256, iend = ibeg + 256;
    for (int i = ibeg; i < iend; i++) {
        float x = base[(size_t)i * L_];
        if (x <= m) {
            s += __expf(x - m);
        } else {
            s = s * __expf(m - x) + 1.f;
            m = x;
        }
    }
    __shared__ float ms[8][32], ss[8][32];
    ms[isl][jt] = m; ss[isl][jt] = s;
    __syncthreads();
    if (isl == 0) {
        float M = m, S = s;
        #pragma unroll
        for (int k = 1; k < 8; k++) {
            float mk = ms[k][jt], sk = ss[k][jt];
            if (mk <= M) {
                S += sk * __expf(mk - M);
            } else {
                S = S * __expf(M - mk) + sk;
                M = mk;
            }
        }
        g_cmax[b * L_ + j] = M;
        g_csumInv[b * L_ + j] = 1.0f / S;
    }
}

// ---------------------------------------------------------------------------
// Apply: P = tf32round(exp(E - rm) * ri), Q = tf32round(exp(E - cm) * ci).
// ---------------------------------------------------------------------------
__global__ __launch_bounds__(256) void k_apply() {
    const int b = blockIdx.y, i = blockIdx.x;
    const float* Erow = g_E + (size_t)(b * L_ + i) * L_;
    float* Prow = g_P + (size_t)(b * L_ + i) * L_;
    float* Qrow = g_Q + (size_t)(b * L_ + i) * L_;
    const float* cmv = g_cmax + b * L_;
    const float* civ = g_csumInv + b * L_;
    const float rm = g_rmax[b * L_ + i];
    const float ri = g_rsumInv[b * L_ + i];

    for (int j = threadIdx.x * 4; j < L_; j += 1024) {
        float4 e = *(const float4*)(Erow + j);
        float4 cm = *(const float4*)(cmv + j);
        float4 ci = *(const float4*)(civ + j);
        float4 p, qv;
        p.x = tf32r(__expf(e.x - rm) * ri);
        p.y = tf32r(__expf(e.y - rm) * ri);
        p.z = tf32r(__expf(e.z - rm) * ri);
        p.w = tf32r(__expf(e.w - rm) * ri);
        qv.x = tf32r(__expf(e.x - cm.x) * ci.x);
        qv.y = tf32r(__expf(e.y - cm.y) * ci.y);
        qv.z = tf32r(__expf(e.z - cm.z) * ci.z);
        qv.w = tf32r(__expf(e.w - cm.w) * ci.w);
        *(float4*)(Prow + j) = p;
        *(float4*)(Qrow + j) = qv;
    }
}

// ---------------------------------------------------------------------------
// a_tilda[i,d] = sum_j P[i,j]*Bt[j,d].  128x128 block, 4 warps (2m x 2n),
// 64x64 warp tile, 128 threads, 2 CTAs/SM, pure cp.async staging.
// ---------------------------------------------------------------------------
#define PPAD 36
#define PBUF (128 * PPAD)
#define KNPAD 136
#define KNBUF (32 * KNPAD)
__global__ __launch_bounds__(128, 2) void k_atilda(float* __restrict__ out) {
    extern __shared__ float sm[];
    float* Ps = sm;
    float* BH = sm + 2 * PBUF;
    const uint32_t uP = smem_u32(Ps), uB = smem_u32(BH);
    const int tid = threadIdx.x, lane = tid & 31, wid = tid >> 5;
    const int wm = wid & 1, wn = wid >> 1;
    const int q = lane >> 2, r = lane & 3;
    const int b = blockIdx.z, i0 = blockIdx.y * 128, d0 = blockIdx.x * 128;
    const float* Pb = g_P + (size_t)b * L_ * L_;
    const float* Btb = g_Bt + (size_t)b * L_ * D_ + d0;

    float acc[4][8][4];
    #pragma unroll
    for (int mt = 0; mt < 4; mt++)
        #pragma unroll
        for (int nt = 0; nt < 8; nt++)
            #pragma unroll
            for (int e = 0; e < 4; e++) acc[mt][nt][e] = 0.f;

    #define STAGE_P(c)                                                                  \
        do {                                                                            \
            const int _buf = (c) & 1, _j0 = (c) * 32;                                   \
            _Pragma("unroll")                                                           \
            for (int t = 0; t < 8; t++) {                                               \
                int idx = t * 128 + tid;                                                \
                int prow = idx >> 3, pch = idx & 7;                                     \
                cpa16(uP + (uint32_t)(_buf * PBUF + prow * PPAD + pch * 4) * 4u,        \
                      Pb + (size_t)(i0 + prow) * L_ + _j0 + pch * 4);                   \
                int brow = idx >> 5, bch = idx & 31;                                    \
                cpa16(uB + (uint32_t)(_buf * KNBUF + brow * KNPAD + bch * 4) * 4u,      \
                      Btb + (size_t)(_j0 + brow) * D_ + bch * 4);                       \
            }                                                                           \
            CP_COMMIT();                                                                \
        } while (0)

    STAGE_P(0);
    for (int c = 0; c < 64; c++) {
        const int buf = c & 1;
        if (c + 1 < 64) { STAGE_P(c + 1); CP_WAIT1(); }
        else            { CP_WAIT0(); }
        __syncthreads();
        const float* P_ = Ps + buf * PBUF;
        const float* BH_ = BH + buf * KNBUF;
        #pragma unroll
        for (int ks = 0; ks < 4; ks++) {
            const int kb = ks * 8;
            uint32_t pa[4][4], bh[8][2];
            #pragma unroll
            for (int mt = 0; mt < 4; mt++) {
                const int rb = wm * 64 + mt * 16;
                pa[mt][0] = __float_as_uint(P_[(rb + q) * PPAD + kb + r]);
                pa[mt][1] = __float_as_uint(P_[(rb + q + 8) * PPAD + kb + r]);
                pa[mt][2] = __float_as_uint(P_[(rb + q) * PPAD + kb + r + 4]);
                pa[mt][3] = __float_as_uint(P_[(rb + q + 8) * PPAD + kb + r + 4]);
            }
            #pragma unroll
            for (int nt = 0; nt < 8; nt++) {
                const int nb = wn * 64 + nt * 8;
                bh[nt][0] = __float_as_uint(BH_[(kb + r) * KNPAD + nb + q]);
                bh[nt][1] = __float_as_uint(BH_[(kb + r + 4) * KNPAD + nb + q]);
            }
            #pragma unroll
            for (int mt = 0; mt < 4; mt++)
                #pragma unroll
                for (int nt = 0; nt < 8; nt++)
                    mma8(acc[mt][nt], pa[mt], bh[nt]);
        }
        __syncthreads();
    }
    #undef STAGE_P

    float* Ob = out + ((size_t)b * L_ + i0) * D_ + d0;
    #pragma unroll
    for (int mt = 0; mt < 4; mt++)
        #pragma unroll
        for (int nt = 0; nt < 8; nt++) {
            int row = wm * 64 + mt * 16 + q;
            int col = wn * 64 + nt * 8 + r * 2;
            *(float2*)(Ob + (size_t)row * D_ + col) =
                make_float2(acc[mt][nt][0], acc[mt][nt][1]);
            *(float2*)(Ob + (size_t)(row + 8) * D_ + col) =
                make_float2(acc[mt][nt][2], acc[mt][nt][3]);
        }
}

// ---------------------------------------------------------------------------
// b_tilda[j,d] = sum_i Q[i,j]*At[i,d].  Same 64x64 warp-tile structure.
// ---------------------------------------------------------------------------
__global__ __launch_bounds__(128, 2) void k_btilda(float* __restrict__ out) {
    extern __shared__ float sm[];
    float* Qs = sm;
    float* AH = sm + 2 * KNBUF;
    const uint32_t uQ = smem_u32(Qs), uA = smem_u32(AH);
    const int tid = threadIdx.x, lane = tid & 31, wid = tid >> 5;
    const int wm = wid & 1, wn = wid >> 1;
    const int q = lane >> 2, r = lane & 3;
    const int b = blockIdx.z, j0 = blockIdx.y * 128, d0 = blockIdx.x * 128;
    const float* Qb = g_Q + (size_t)b * L_ * L_ + j0;
    const float* Atb = g_At + (size_t)b * L_ * D_ + d0;

    float acc[4][8][4];
    #pragma unroll
    for (int mt = 0; mt < 4; mt++)
        #pragma unroll
        for (int nt = 0; nt < 8; nt++)
            #pragma unroll
            for (int e = 0; e < 4; e++) acc[mt][nt][e] = 0.f;

    #define STAGE_Q(c)                                                                  \
        do {                                                                            \
            const int _buf = (c) & 1, _i0 = (c) * 32;                                   \
            _Pragma("unroll")                                                           \
            for (int t = 0; t < 8; t++) {                                               \
                int idx = t * 128 + tid;                                                \
                int row = idx >> 5, ch = idx & 31;                                      \
                cpa16(uQ + (uint32_t)(_buf * KNBUF + row * KNPAD + ch * 4) * 4u,        \
                      Qb + (size_t)(_i0 + row) * L_ + ch * 4);                          \
                cpa16(uA + (uint32_t)(_buf * KNBUF + row * KNPAD + ch * 4) * 4u,        \
                      Atb + (size_t)(_i0 + row) * D_ + ch * 4);                         \
            }                                                                           \
            CP_COMMIT();                                                                \
        } while (0)

    STAGE_Q(0);
    for (int c = 0; c < 64; c++) {
        const int buf = c & 1;
        if (c + 1 < 64) { STAGE_Q(c + 1); CP_WAIT1(); }
        else            { CP_WAIT0(); }
        __syncthreads();
        const float* Q_ = Qs + buf * KNBUF;
        const float* AH_ = AH + buf * KNBUF;
        #pragma unroll
        for (int ks = 0; ks < 4; ks++) {
            const int kb = ks * 8;
            uint32_t qa[4][4], bh[8][2];
            #pragma unroll
            for (int mt = 0; mt < 4; mt++) {
                const int mb = wm * 64 + mt * 16;
                qa[mt][0] = __float_as_uint(Q_[(kb + r) * KNPAD + mb + q]);
                qa[mt][1] = __float_as_uint(Q_[(kb + r) * KNPAD + mb + q + 8]);
                qa[mt][2] = __float_as_uint(Q_[(kb + r + 4) * KNPAD + mb + q]);
                qa[mt][3] = __float_as_uint(Q_[(kb + r + 4) * KNPAD + mb + q + 8]);
            }
            #pragma unroll
            for (int nt = 0; nt < 8; nt++) {
                const int nb = wn * 64 + nt * 8;
                bh[nt][0] = __float_as_uint(AH_[(kb + r) * KNPAD + nb + q]);
                bh[nt][1] = __float_as_uint(AH_[(kb + r + 4) * KNPAD + nb + q]);
            }
            #pragma unroll
            for (int mt = 0; mt < 4; mt++)
                #pragma unroll
                for (int nt = 0; nt < 8; nt++)
                    mma8(acc[mt][nt], qa[mt], bh[nt]);
        }
        __syncthreads();
    }
    #undef STAGE_Q

    float* Ob = out + ((size_t)b * L_ + j0) * D_ + d0;
    #pragma unroll
    for (int mt = 0; mt < 4; mt++)
        #pragma unroll
        for (int nt = 0; nt < 8; nt++) {
            int row = wm * 64 + mt * 16 + q;
            int col = wn * 64 + nt * 8 + r * 2;
            *(float2*)(Ob + (size_t)row * D_ + col) =
                make_float2(acc[mt][nt][0], acc[mt][nt][1]);
            *(float2*)(Ob + (size_t)(row + 8) * D_ + col) =
                make_float2(acc[mt][nt][2], acc[mt][nt][3]);
        }
}

// ---------------------------------------------------------------------------
extern "C" void kernel_launch(void* const* d_in, const int* in_sizes, int n_in,
                              void* d_out, int out_size) {
    const float* A = (const float*)d_in[0];
    const float* B = (const float*)d_in[1];
    float* out = (float*)d_out;
    float* a_tilda = out;
    float* b_tilda = out + (size_t)BN_ * L_ * D_;

    const int SMEM_E = 8 * EB2 * 4;                             // 81920 B
    const int SMEM_A = (2 * PBUF + 2 * KNBUF) * 4;              // 71680 B
    const int SMEM_B = (4 * KNBUF) * 4;                         // 69632 B
    cudaFuncSetAttribute(k_gemm_e, cudaFuncAttributeMaxDynamicSharedMemorySize, SMEM_E);
    cudaFuncSetAttribute(k_atilda, cudaFuncAttributeMaxDynamicSharedMemorySize, SMEM_A);
    cudaFuncSetAttribute(k_btilda, cudaFuncAttributeMaxDynamicSharedMemorySize, SMEM_B);

    k_round<<<(BN_ * L_ * D_) / 1024, 256>>>(A, B);
    k_gemm_e<<<dim3(L_ / 128, L_ / 128, BN_), 256, SMEM_E>>>(A, B);
    k_rowstats<<<dim3(L_, BN_), 256>>>();
    k_colstats<<<dim3(L_ / 32, BN_), 256>>>();
    k_apply<<<dim3(L_, BN_), 256>>>();
    k_atilda<<<dim3(D_ / 128, L_ / 128, BN_), 128, SMEM_A>>>(a_tilda);
    k_btilda<<<dim3(D_ / 128, L_ / 128, BN_), 128, SMEM_B>>>(b_tilda);
}

// round 17
// speedup vs baseline: 1.2364x; 1.0834x over previous
#include <cuda_runtime.h>
#include <math.h>
#include <stdint.h>

#define BN_ 8
#define L_ 2048
#define D_ 1024

// Scratch
__device__ float g_E[(size_t)BN_ * L_ * L_];
__device__ float g_P[(size_t)BN_ * L_ * L_];   // row-softmax(E), tf32-rounded
__device__ float g_Q[(size_t)BN_ * L_ * L_];   // col-softmax(E), tf32-rounded
__device__ float g_At[(size_t)BN_ * L_ * D_];  // tf32-rounded A
__device__ float g_Bt[(size_t)BN_ * L_ * D_];  // tf32-rounded B
__device__ float g_rmax[BN_ * L_];
__device__ float g_rsumInv[BN_ * L_];
__device__ float g_cmax[BN_ * L_];
__device__ float g_csumInv[BN_ * L_];

#define NEG_INF __int_as_float(0xff800000)

static __device__ __forceinline__ uint32_t smem_u32(const void* p) {
    uint32_t a;
    asm("{ .reg .u64 t; cvta.to.shared.u64 t, %1; cvt.u32.u64 %0, t; }"
        : "=r"(a) : "l"(p));
    return a;
}
static __device__ __forceinline__ uint32_t cvt_tf32(float x) {
    uint32_t h;
    asm("cvt.rna.tf32.f32 %0, %1;" : "=r"(h) : "f"(x));
    return h;
}
static __device__ __forceinline__ float tf32r(float x) {
    return __uint_as_float(cvt_tf32(x));
}
static __device__ __forceinline__ uint32_t bf2(float lo, float hi) {
    uint32_t d;
    asm("cvt.rn.bf16x2.f32 %0, %1, %2;" : "=r"(d) : "f"(hi), "f"(lo));
    return d;
}
static __device__ __forceinline__ float bflo(uint32_t p) { return __uint_as_float(p << 16); }
static __device__ __forceinline__ float bfhi(uint32_t p) { return __uint_as_float(p & 0xffff0000u); }

static __device__ __forceinline__ void mma8(float c[4], const uint32_t a[4],
                                            const uint32_t b[2]) {
    asm volatile(
        "mma.sync.aligned.m16n8k8.row.col.f32.tf32.tf32.f32 "
        "{%0,%1,%2,%3},{%4,%5,%6,%7},{%8,%9},{%0,%1,%2,%3};"
        : "+f"(c[0]), "+f"(c[1]), "+f"(c[2]), "+f"(c[3])
        : "r"(a[0]), "r"(a[1]), "r"(a[2]), "r"(a[3]), "r"(b[0]), "r"(b[1]));
}
static __device__ __forceinline__ void mma16(float c[4], const uint32_t a[4],
                                             const uint32_t b[2]) {
    asm volatile(
        "mma.sync.aligned.m16n8k16.row.col.f32.bf16.bf16.f32 "
        "{%0,%1,%2,%3},{%4,%5,%6,%7},{%8,%9},{%0,%1,%2,%3};"
        : "+f"(c[0]), "+f"(c[1]), "+f"(c[2]), "+f"(c[3])
        : "r"(a[0]), "r"(a[1]), "r"(a[2]), "r"(a[3]), "r"(b[0]), "r"(b[1]));
}
static __device__ __forceinline__ void cpa16(uint32_t dst, const void* src) {
    asm volatile("cp.async.cg.shared.global [%0], [%1], 16;" :: "r"(dst), "l"(src));
}
#define CP_COMMIT() asm volatile("cp.async.commit_group;" ::: "memory")
#define CP_WAIT1()  asm volatile("cp.async.wait_group 1;" ::: "memory")
#define CP_WAIT0()  asm volatile("cp.async.wait_group 0;" ::: "memory")

// ---------------------------------------------------------------------------
// Round A, B to tf32 once (for phase-2).
// ---------------------------------------------------------------------------
__global__ __launch_bounds__(256) void k_round(const float* __restrict__ A,
                                               const float* __restrict__ B) {
    const size_t i = ((size_t)blockIdx.x * 256 + threadIdx.x) * 4;
    float4 a = *(const float4*)(A + i);
    float4 b = *(const float4*)(B + i);
    a.x = tf32r(a.x); a.y = tf32r(a.y); a.z = tf32r(a.z); a.w = tf32r(a.w);
    b.x = tf32r(b.x); b.y = tf32r(b.y); b.z = tf32r(b.z); b.w = tf32r(b.w);
    *(float4*)(g_At + i) = a;
    *(float4*)(g_Bt + i) = b;
}

// ---------------------------------------------------------------------------
// E = A @ B^T via 3xBF16 (hh + hl + lh), m16n8k16. 128x128 block, BK=32,
// 4 warps (2m x 2n), 64x64 warp tile, 128 threads, 2 CTAs/SM.
// Staging: direct LDG -> split -> STS (no prefetch regs).
// ---------------------------------------------------------------------------
#define EP2 20
#define EB2 (128 * EP2)
__global__ __launch_bounds__(128, 2) void k_gemm_e(const float* __restrict__ A,
                                                   const float* __restrict__ B) {
    extern __shared__ uint32_t smu[];
    uint32_t* tAH = smu;
    uint32_t* tAL = smu + 2 * EB2;
    uint32_t* tBH = smu + 4 * EB2;
    uint32_t* tBL = smu + 6 * EB2;
    const int tid = threadIdx.x, lane = tid & 31, wid = tid >> 5;
    const int wm = wid & 1, wn = wid >> 1;
    const int q = lane >> 2, r = lane & 3;
    const int b = blockIdx.z, i0 = blockIdx.y * 128, j0 = blockIdx.x * 128;
    const float* Ab = A + ((size_t)b * L_ + i0) * D_;
    const float* Bb = B + ((size_t)b * L_ + j0) * D_;

    float acc[4][8][4];
    #pragma unroll
    for (int mt = 0; mt < 4; mt++)
        #pragma unroll
        for (int nt = 0; nt < 8; nt++)
            #pragma unroll
            for (int e = 0; e < 4; e++) acc[mt][nt][e] = 0.f;

    const int srow = tid >> 2;        // 0..31
    const int sc4 = tid & 3;          // 8-float k-group

    #define PACKSTORE(dstH, dstL, v0, v1, off)                                          \
        do {                                                                            \
            uint32_t h0 = bf2((v0).x, (v0).y), h1 = bf2((v0).z, (v0).w);                \
            uint32_t h2 = bf2((v1).x, (v1).y), h3 = bf2((v1).z, (v1).w);                \
            uint32_t l0 = bf2((v0).x - bflo(h0), (v0).y - bfhi(h0));                    \
            uint32_t l1 = bf2((v0).z - bflo(h1), (v0).w - bfhi(h1));                    \
            uint32_t l2 = bf2((v1).x - bflo(h2), (v1).y - bfhi(h2));                    \
            uint32_t l3 = bf2((v1).z - bflo(h3), (v1).w - bfhi(h3));                    \
            *(uint4*)((dstH) + (off)) = make_uint4(h0, h1, h2, h3);                     \
            *(uint4*)((dstL) + (off)) = make_uint4(l0, l1, l2, l3);                     \
        } while (0)
    // stage chunk c into buffer bufn: direct LDG -> split -> STS
    #define STAGE_E(c, bufn)                                                           \
        do {                                                                           \
            const int _k0 = (c) * 32 + sc4 * 8;                                        \
            _Pragma("unroll")                                                          \
            for (int t = 0; t < 4; t++) {                                              \
                int row = t * 32 + srow;                                               \
                float4 v0 = *(const float4*)(Ab + (size_t)row * D_ + _k0);             \
                float4 v1 = *(const float4*)(Ab + (size_t)row * D_ + _k0 + 4);         \
                float4 w0 = *(const float4*)(Bb + (size_t)row * D_ + _k0);             \
                float4 w1 = *(const float4*)(Bb + (size_t)row * D_ + _k0 + 4);         \
                int off = (bufn) * EB2 + row * EP2 + sc4 * 4;                          \
                PACKSTORE(tAH, tAL, v0, v1, off);                                      \
                PACKSTORE(tBH, tBL, w0, w1, off);                                      \
            }                                                                          \
        } while (0)

    STAGE_E(0, 0);
    for (int c = 0; c < 32; c++) {
        const int buf = c & 1;
        __syncthreads();   // buf ready (written before loop or at end of prev iter)
        const uint32_t* AH_ = tAH + buf * EB2;
        const uint32_t* AL_ = tAL + buf * EB2;
        const uint32_t* BH_ = tBH + buf * EB2;
        const uint32_t* BL_ = tBL + buf * EB2;
        #pragma unroll
        for (int ks = 0; ks < 2; ks++) {
            const int kb2 = ks * 8;
            uint32_t ah[4][4], al[4][4], bh[8][2], bl[8][2];
            #pragma unroll
            for (int mt = 0; mt < 4; mt++) {
                const int rb = wm * 64 + mt * 16;
                ah[mt][0] = AH_[(rb + q) * EP2 + kb2 + r];
                ah[mt][1] = AH_[(rb + q + 8) * EP2 + kb2 + r];
                ah[mt][2] = AH_[(rb + q) * EP2 + kb2 + r + 4];
                ah[mt][3] = AH_[(rb + q + 8) * EP2 + kb2 + r + 4];
                al[mt][0] = AL_[(rb + q) * EP2 + kb2 + r];
                al[mt][1] = AL_[(rb + q + 8) * EP2 + kb2 + r];
                al[mt][2] = AL_[(rb + q) * EP2 + kb2 + r + 4];
                al[mt][3] = AL_[(rb + q + 8) * EP2 + kb2 + r + 4];
            }
            #pragma unroll
            for (int nt = 0; nt < 8; nt++) {
                const int nb = wn * 64 + nt * 8;
                bh[nt][0] = BH_[(nb + q) * EP2 + kb2 + r];
                bh[nt][1] = BH_[(nb + q) * EP2 + kb2 + r + 4];
                bl[nt][0] = BL_[(nb + q) * EP2 + kb2 + r];
                bl[nt][1] = BL_[(nb + q) * EP2 + kb2 + r + 4];
            }
            #pragma unroll
            for (int mt = 0; mt < 4; mt++)
                #pragma unroll
                for (int nt = 0; nt < 8; nt++) {
                    mma16(acc[mt][nt], al[mt], bh[nt]);
                    mma16(acc[mt][nt], ah[mt], bl[nt]);
                    mma16(acc[mt][nt], ah[mt], bh[nt]);
                }
        }
        if (c + 1 < 32) {
            STAGE_E(c + 1, buf ^ 1);   // write other buffer; no hazard with reads of buf
        }
    }
    #undef STAGE_E
    #undef PACKSTORE

    float* Eb = g_E + ((size_t)b * L_ + i0) * L_ + j0;
    #pragma unroll
    for (int mt = 0; mt < 4; mt++)
        #pragma unroll
        for (int nt = 0; nt < 8; nt++) {
            int row = wm * 64 + mt * 16 + q;
            int col = wn * 64 + nt * 8 + r * 2;
            *(float2*)(Eb + (size_t)row * L_ + col) =
                make_float2(acc[mt][nt][0], acc[mt][nt][1]);
            *(float2*)(Eb + (size_t)(row + 8) * L_ + col) =
                make_float2(acc[mt][nt][2], acc[mt][nt][3]);
        }
}

// ---------------------------------------------------------------------------
// Row / col softmax stats
// ---------------------------------------------------------------------------
__global__ __launch_bounds__(256) void k_rowstats() {
    const int b = blockIdx.y, rrow = blockIdx.x;
    const float* row = g_E + (size_t)(b * L_ + rrow) * L_;
    const int tid = threadIdx.x;
    __shared__ float red[256];

    float m = NEG_INF;
    for (int j = tid * 4; j < L_; j += 1024) {
        float4 v = *(const float4*)(row + j);
        m = fmaxf(m, fmaxf(fmaxf(v.x, v.y), fmaxf(v.z, v.w)));
    }
    red[tid] = m; __syncthreads();
    for (int s = 128; s >= 1; s >>= 1) {
        if (tid < s) red[tid] = fmaxf(red[tid], red[tid + s]);
        __syncthreads();
    }
    const float M = red[0];
    __syncthreads();

    float sum = 0.f;
    for (int j = tid * 4; j < L_; j += 1024) {
        float4 v = *(const float4*)(row + j);
        sum += __expf(v.x - M) + __expf(v.y - M) + __expf(v.z - M) + __expf(v.w - M);
    }
    red[tid] = sum; __syncthreads();
    for (int s = 128; s >= 1; s >>= 1) {
        if (tid < s) red[tid] += red[tid + s];
        __syncthreads();
    }
    if (tid == 0) {
        g_rmax[b * L_ + rrow] = M;
        g_rsumInv[b * L_ + rrow] = 1.0f / red[0];
    }
}

__global__ __launch_bounds__(256) void k_colstats() {
    const int b = blockIdx.y;
    const int jt = threadIdx.x & 31;
    const int isl = threadIdx.x >> 5;
    const int j = blockIdx.x * 32 + jt;
    const float* base = g_E + (size_t)b * L_ * L_ + j;

    float m = NEG_INF, s = 0.f;
    const int ibeg = isl * 256, iend = ibeg + 256;
    for (int i = ibeg; i < iend; i++) {
        float x = base[(size_t)i * L_];
        if (x <= m) {
            s += __expf(x - m);
        } else {
            s = s * __expf(m - x) + 1.f;
            m = x;
        }
    }
    __shared__ float ms[8][32], ss[8][32];
    ms[isl][jt] = m; ss[isl][jt] = s;
    __syncthreads();
    if (isl == 0) {
        float M = m, S = s;
        #pragma unroll
        for (int k = 1; k < 8; k++) {
            float mk = ms[k][jt], sk = ss[k][jt];
            if (mk <= M) {
                S += sk * __expf(mk - M);
            } else {
                S = S * __expf(M - mk) + sk;
                M = mk;
            }
        }
        g_cmax[b * L_ + j] = M;
        g_csumInv[b * L_ + j] = 1.0f / S;
    }
}

// ---------------------------------------------------------------------------
// Apply: P = tf32round(exp(E - rm) * ri), Q = tf32round(exp(E - cm) * ci).
// ---------------------------------------------------------------------------
__global__ __launch_bounds__(256) void k_apply() {
    const int b = blockIdx.y, i = blockIdx.x;
    const float* Erow = g_E + (size_t)(b * L_ + i) * L_;
    float* Prow = g_P + (size_t)(b * L_ + i) * L_;
    float* Qrow = g_Q + (size_t)(b * L_ + i) * L_;
    const float* cmv = g_cmax + b * L_;
    const float* civ = g_csumInv + b * L_;
    const float rm = g_rmax[b * L_ + i];
    const float ri = g_rsumInv[b * L_ + i];

    for (int j = threadIdx.x * 4; j < L_; j += 1024) {
        float4 e = *(const float4*)(Erow + j);
        float4 cm = *(const float4*)(cmv + j);
        float4 ci = *(const float4*)(civ + j);
        float4 p, qv;
        p.x = tf32r(__expf(e.x - rm) * ri);
        p.y = tf32r(__expf(e.y - rm) * ri);
        p.z = tf32r(__expf(e.z - rm) * ri);
        p.w = tf32r(__expf(e.w - rm) * ri);
        qv.x = tf32r(__expf(e.x - cm.x) * ci.x);
        qv.y = tf32r(__expf(e.y - cm.y) * ci.y);
        qv.z = tf32r(__expf(e.z - cm.z) * ci.z);
        qv.w = tf32r(__expf(e.w - cm.w) * ci.w);
        *(float4*)(Prow + j) = p;
        *(float4*)(Qrow + j) = qv;
    }
}

// ---------------------------------------------------------------------------
// a_tilda[i,d] = sum_j P[i,j]*Bt[j,d].  128x128 block, 4 warps (2m x 2n),
// 64x64 warp tile, 128 threads, 2 CTAs/SM, pure cp.async staging.
// ---------------------------------------------------------------------------
#define PPAD 36
#define PBUF (128 * PPAD)
#define KNPAD 136
#define KNBUF (32 * KNPAD)
__global__ __launch_bounds__(128, 2) void k_atilda(float* __restrict__ out) {
    extern __shared__ float sm[];
    float* Ps = sm;
    float* BH = sm + 2 * PBUF;
    const uint32_t uP = smem_u32(Ps), uB = smem_u32(BH);
    const int tid = threadIdx.x, lane = tid & 31, wid = tid >> 5;
    const int wm = wid & 1, wn = wid >> 1;
    const int q = lane >> 2, r = lane & 3;
    const int b = blockIdx.z, i0 = blockIdx.y * 128, d0 = blockIdx.x * 128;
    const float* Pb = g_P + (size_t)b * L_ * L_;
    const float* Btb = g_Bt + (size_t)b * L_ * D_ + d0;

    float acc[4][8][4];
    #pragma unroll
    for (int mt = 0; mt < 4; mt++)
        #pragma unroll
        for (int nt = 0; nt < 8; nt++)
            #pragma unroll
            for (int e = 0; e < 4; e++) acc[mt][nt][e] = 0.f;

    #define STAGE_P(c)                                                                  \
        do {                                                                            \
            const int _buf = (c) & 1, _j0 = (c) * 32;                                   \
            _Pragma("unroll")                                                           \
            for (int t = 0; t < 8; t++) {                                               \
                int idx = t * 128 + tid;                                                \
                int prow = idx >> 3, pch = idx & 7;                                     \
                cpa16(uP + (uint32_t)(_buf * PBUF + prow * PPAD + pch * 4) * 4u,        \
                      Pb + (size_t)(i0 + prow) * L_ + _j0 + pch * 4);                   \
                int brow = idx >> 5, bch = idx & 31;                                    \
                cpa16(uB + (uint32_t)(_buf * KNBUF + brow * KNPAD + bch * 4) * 4u,      \
                      Btb + (size_t)(_j0 + brow) * D_ + bch * 4);                       \
            }                                                                           \
            CP_COMMIT();                                                                \
        } while (0)

    STAGE_P(0);
    for (int c = 0; c < 64; c++) {
        const int buf = c & 1;
        if (c + 1 < 64) { STAGE_P(c + 1); CP_WAIT1(); }
        else            { CP_WAIT0(); }
        __syncthreads();
        const float* P_ = Ps + buf * PBUF;
        const float* BH_ = BH + buf * KNBUF;
        #pragma unroll
        for (int ks = 0; ks < 4; ks++) {
            const int kb = ks * 8;
            uint32_t pa[4][4], bh[8][2];
            #pragma unroll
            for (int mt = 0; mt < 4; mt++) {
                const int rb = wm * 64 + mt * 16;
                pa[mt][0] = __float_as_uint(P_[(rb + q) * PPAD + kb + r]);
                pa[mt][1] = __float_as_uint(P_[(rb + q + 8) * PPAD + kb + r]);
                pa[mt][2] = __float_as_uint(P_[(rb + q) * PPAD + kb + r + 4]);
                pa[mt][3] = __float_as_uint(P_[(rb + q + 8) * PPAD + kb + r + 4]);
            }
            #pragma unroll
            for (int nt = 0; nt < 8; nt++) {
                const int nb = wn * 64 + nt * 8;
                bh[nt][0] = __float_as_uint(BH_[(kb + r) * KNPAD + nb + q]);
                bh[nt][1] = __float_as_uint(BH_[(kb + r + 4) * KNPAD + nb + q]);
            }
            #pragma unroll
            for (int mt = 0; mt < 4; mt++)
                #pragma unroll
                for (int nt = 0; nt < 8; nt++)
                    mma8(acc[mt][nt], pa[mt], bh[nt]);
        }
        __syncthreads();
    }
    #undef STAGE_P

    float* Ob = out + ((size_t)b * L_ + i0) * D_ + d0;
    #pragma unroll
    for (int mt = 0; mt < 4; mt++)
        #pragma unroll
        for (int nt = 0; nt < 8; nt++) {
            int row = wm * 64 + mt * 16 + q;
            int col = wn * 64 + nt * 8 + r * 2;
            *(float2*)(Ob + (size_t)row * D_ + col) =
                make_float2(acc[mt][nt][0], acc[mt][nt][1]);
            *(float2*)(Ob + (size_t)(row + 8) * D_ + col) =
                make_float2(acc[mt][nt][2], acc[mt][nt][3]);
        }
}

// ---------------------------------------------------------------------------
// b_tilda[j,d] = sum_i Q[i,j]*At[i,d].  Same 64x64 warp-tile structure.
// ---------------------------------------------------------------------------
__global__ __launch_bounds__(128, 2) void k_btilda(float* __restrict__ out) {
    extern __shared__ float sm[];
    float* Qs = sm;
    float* AH = sm + 2 * KNBUF;
    const uint32_t uQ = smem_u32(Qs), uA = smem_u32(AH);
    const int tid = threadIdx.x, lane = tid & 31, wid = tid >> 5;
    const int wm = wid & 1, wn = wid >> 1;
    const int q = lane >> 2, r = lane & 3;
    const int b = blockIdx.z, j0 = blockIdx.y * 128, d0 = blockIdx.x * 128;
    const float* Qb = g_Q + (size_t)b * L_ * L_ + j0;
    const float* Atb = g_At + (size_t)b * L_ * D_ + d0;

    float acc[4][8][4];
    #pragma unroll
    for (int mt = 0; mt < 4; mt++)
        #pragma unroll
        for (int nt = 0; nt < 8; nt++)
            #pragma unroll
            for (int e = 0; e < 4; e++) acc[mt][nt][e] = 0.f;

    #define STAGE_Q(c)                                                                  \
        do {                                                                            \
            const int _buf = (c) & 1, _i0 = (c) * 32;                                   \
            _Pragma("unroll")                                                           \
            for (int t = 0; t < 8; t++) {                                               \
                int idx = t * 128 + tid;                                                \
                int row = idx >> 5, ch = idx & 31;                                      \
                cpa16(uQ + (uint32_t)(_buf * KNBUF + row * KNPAD + ch * 4) * 4u,        \
                      Qb + (size_t)(_i0 + row) * L_ + ch * 4);                          \
                cpa16(uA + (uint32_t)(_buf * KNBUF + row * KNPAD + ch * 4) * 4u,        \
                      Atb + (size_t)(_i0 + row) * D_ + ch * 4);                         \
            }                                                                           \
            CP_COMMIT();                                                                \
        } while (0)

    STAGE_Q(0);
    for (int c = 0; c < 64; c++) {
        const int buf = c & 1;
        if (c + 1 < 64) { STAGE_Q(c + 1); CP_WAIT1(); }
        else            { CP_WAIT0(); }
        __syncthreads();
        const float* Q_ = Qs + buf * KNBUF;
        const float* AH_ = AH + buf * KNBUF;
        #pragma unroll
        for (int ks = 0; ks < 4; ks++) {
            const int kb = ks * 8;
            uint32_t qa[4][4], bh[8][2];
            #pragma unroll
            for (int mt = 0; mt < 4; mt++) {
                const int mb = wm * 64 + mt * 16;
                qa[mt][0] = __float_as_uint(Q_[(kb + r) * KNPAD + mb + q]);
                qa[mt][1] = __float_as_uint(Q_[(kb + r) * KNPAD + mb + q + 8]);
                qa[mt][2] = __float_as_uint(Q_[(kb + r + 4) * KNPAD + mb + q]);
                qa[mt][3] = __float_as_uint(Q_[(kb + r + 4) * KNPAD + mb + q + 8]);
            }
            #pragma unroll
            for (int nt = 0; nt < 8; nt++) {
                const int nb = wn * 64 + nt * 8;
                bh[nt][0] = __float_as_uint(AH_[(kb + r) * KNPAD + nb + q]);
                bh[nt][1] = __float_as_uint(AH_[(kb + r + 4) * KNPAD + nb + q]);
            }
            #pragma unroll
            for (int mt = 0; mt < 4; mt++)
                #pragma unroll
                for (int nt = 0; nt < 8; nt++)
                    mma8(acc[mt][nt], qa[mt], bh[nt]);
        }
        __syncthreads();
    }
    #undef STAGE_Q

    float* Ob = out + ((size_t)b * L_ + j0) * D_ + d0;
    #pragma unroll
    for (int mt = 0; mt < 4; mt++)
        #pragma unroll
        for (int nt = 0; nt < 8; nt++) {
            int row = wm * 64 + mt * 16 + q;
            int col = wn * 64 + nt * 8 + r * 2;
            *(float2*)(Ob + (size_t)row * D_ + col) =
                make_float2(acc[mt][nt][0], acc[mt][nt][1]);
            *(float2*)(Ob + (size_t)(row + 8) * D_ + col) =
                make_float2(acc[mt][nt][2], acc[mt][nt][3]);
        }
}

// ---------------------------------------------------------------------------
extern "C" void kernel_launch(void* const* d_in, const int* in_sizes, int n_in,
                              void* d_out, int out_size) {
    const float* A = (const float*)d_in[0];
    const float* B = (const float*)d_in[1];
    float* out = (float*)d_out;
    float* a_tilda = out;
    float* b_tilda = out + (size_t)BN_ * L_ * D_;

    const int SMEM_E = 8 * EB2 * 4;                             // 81920 B
    const int SMEM_A = (2 * PBUF + 2 * KNBUF) * 4;              // 71680 B
    const int SMEM_B = (4 * KNBUF) * 4;                         // 69632 B
    cudaFuncSetAttribute(k_gemm_e, cudaFuncAttributeMaxDynamicSharedMemorySize, SMEM_E);
    cudaFuncSetAttribute(k_atilda, cudaFuncAttributeMaxDynamicSharedMemorySize, SMEM_A);
    cudaFuncSetAttribute(k_btilda, cudaFuncAttributeMaxDynamicSharedMemorySize, SMEM_B);

    k_round<<<(BN_ * L_ * D_) / 1024, 256>>>(A, B);
    k_gemm_e<<<dim3(L_ / 128, L_ / 128, BN_), 128, SMEM_E>>>(A, B);
    k_rowstats<<<dim3(L_, BN_), 256>>>();
    k_colstats<<<dim3(L_ / 32, BN_), 256>>>();
    k_apply<<<dim3(L_, BN_), 256>>>();
    k_atilda<<<dim3(D_ / 128, L_ / 128, BN_), 128, SMEM_A>>>(a_tilda);
    k_btilda<<<dim3(D_ / 128, L_ / 128, BN_), 128, SMEM_B>>>(b_tilda);
}